// round 1
// baseline (speedup 1.0000x reference)
#include <cuda_runtime.h>
#include <math.h>

#define NB 2
#define NS 2048
#define ND 2048
#define NH 16
#define NDH 128
#define NM (NB*NS)

// Scratch (device globals; no allocation allowed)
__device__ float g_q[(size_t)NB*NH*NS*NDH];
__device__ float g_k[(size_t)NB*NH*NS*NDH];
__device__ float g_v[(size_t)NB*NH*NS*NDH];
__device__ float g_ctx[(size_t)NB*NS*ND];

// C[M,N] = A[M,K] * W[N,K]^T  (NT gemm), M=4096, N=K=2048
// MODE 0: plain row-major store to C[M,N]
// MODE 1: scatter to heads layout [b,h,s,dh]
// MODE 2: scatter to heads layout + fused RoPE
template<int MODE>
__global__ void __launch_bounds__(256) gemm_nt(
    const float* __restrict__ A, const float* __restrict__ W,
    float* __restrict__ C,
    const float* __restrict__ fcos, const float* __restrict__ fsin)
{
  __shared__ float As[128][17];
  __shared__ float Bs[128][17];
  const int K = ND;
  const int bm = blockIdx.y * 128;
  const int bn = blockIdx.x * 128;
  const int tid = threadIdx.x;
  const int tx = tid & 15, ty = tid >> 4;

  float acc[8][8];
  #pragma unroll
  for (int i = 0; i < 8; i++)
    #pragma unroll
    for (int j = 0; j < 8; j++) acc[i][j] = 0.f;

  const int lr = tid >> 1;          // 0..127
  const int lk = (tid & 1) * 8;     // 0 or 8
  const float* ap = A + (size_t)(bm + lr) * K + lk;
  const float* wp = W + (size_t)(bn + lr) * K + lk;

  for (int k0 = 0; k0 < K; k0 += 16) {
    #pragma unroll
    for (int i = 0; i < 8; i++) As[lr][lk + i] = ap[k0 + i];
    #pragma unroll
    for (int i = 0; i < 8; i++) Bs[lr][lk + i] = wp[k0 + i];
    __syncthreads();
    #pragma unroll
    for (int kk = 0; kk < 16; kk++) {
      float af[8], bf[8];
      #pragma unroll
      for (int i = 0; i < 8; i++) af[i] = As[ty * 8 + i][kk];
      #pragma unroll
      for (int j = 0; j < 8; j++) bf[j] = Bs[tx * 8 + j][kk];
      #pragma unroll
      for (int i = 0; i < 8; i++)
        #pragma unroll
        for (int j = 0; j < 8; j++)
          acc[i][j] = fmaf(af[i], bf[j], acc[i][j]);
    }
    __syncthreads();
  }

  #pragma unroll
  for (int i = 0; i < 8; i++) {
    const int m = bm + ty * 8 + i;
    const int b = m / NS, s = m % NS;
    if (MODE == 0) {
      float* cp = C + (size_t)m * ND + bn + tx * 8;
      #pragma unroll
      for (int j = 0; j < 8; j++) cp[j] = acc[i][j];
    } else if (MODE == 1) {
      #pragma unroll
      for (int j = 0; j < 8; j++) {
        const int n = bn + tx * 8 + j;
        const int h = n / NDH, d = n % NDH;
        float* dst = C + (((size_t)(b * NH + h)) * NS + s) * NDH;
        dst[d] = acc[i][j];
      }
    } else {
      #pragma unroll
      for (int j = 0; j < 8; j += 2) {
        const int n = bn + tx * 8 + j;   // even (tx*8 aligned)
        const int h = n / NDH, d = n % NDH;
        float* dst = C + (((size_t)(b * NH + h)) * NS + s) * NDH;
        const int pi = d >> 1;
        const float c  = fcos[s * (NDH / 2) + pi];
        const float sn = fsin[s * (NDH / 2) + pi];
        const float a0 = acc[i][j], a1 = acc[i][j + 1];
        dst[d]     = a0 * c  - a1 * sn;
        dst[d + 1] = a0 * sn + a1 * c;
      }
    }
  }
}

// Flash attention, causal, fp32.
// Block: 64 query rows, 256 threads; 4 threads per row, each owning 32
// interleaved dims (d_global = seg + 4*d). Key tiles of 32 in smem.
__global__ void __launch_bounds__(256) flash_kernel(
    const float* __restrict__ gq, const float* __restrict__ gk,
    const float* __restrict__ gv, float* __restrict__ ctx)
{
  const int bh = blockIdx.y;
  const int b = bh / NH, h = bh % NH;
  const int qbase = blockIdx.x * 64;
  const int tid = threadIdx.x;
  const int row = tid >> 2;
  const int seg = tid & 3;
  const int qrow = qbase + row;

  const float* qptr = gq + ((size_t)bh * NS + qrow) * NDH;
  float qr[32], o[32];
  #pragma unroll
  for (int d = 0; d < 32; d++) {
    qr[d] = qptr[seg + 4 * d];
    o[d] = 0.f;
  }
  float mrow = -1e30f, l = 0.f;

  __shared__ float Ks[32][128];
  __shared__ float Vs[32][128];
  const float* kbp = gk + (size_t)bh * NS * NDH;
  const float* vbp = gv + (size_t)bh * NS * NDH;
  const int ntiles = qbase / 32 + 2;
  const float scale = 0.08838834764831845f;  // 1/sqrt(128)

  for (int t = 0; t < ntiles; t++) {
    const int k0 = t * 32;
    __syncthreads();
    // cooperative tile load: 32*128 floats = 1024 float4 each
    const float4* ksrc = (const float4*)(kbp + (size_t)k0 * NDH);
    const float4* vsrc = (const float4*)(vbp + (size_t)k0 * NDH);
    float4* kdst = (float4*)&Ks[0][0];
    float4* vdst = (float4*)&Vs[0][0];
    #pragma unroll
    for (int i = 0; i < 4; i++) {
      kdst[tid + 256 * i] = ksrc[tid + 256 * i];
      vdst[tid + 256 * i] = vsrc[tid + 256 * i];
    }
    __syncthreads();

    float sc[32];
    #pragma unroll
    for (int j = 0; j < 32; j++) {
      float s = 0.f;
      #pragma unroll
      for (int d = 0; d < 32; d++) s = fmaf(qr[d], Ks[j][seg + 4 * d], s);
      // reduce across the 4 dim-segment threads (consecutive lanes)
      s += __shfl_xor_sync(0xffffffffu, s, 1);
      s += __shfl_xor_sync(0xffffffffu, s, 2);
      sc[j] = (k0 + j <= qrow) ? s * scale : -1e30f;
    }
    float mt = mrow;
    #pragma unroll
    for (int j = 0; j < 32; j++) mt = fmaxf(mt, sc[j]);
    const float alpha = __expf(mrow - mt);
    mrow = mt;
    l *= alpha;
    #pragma unroll
    for (int d = 0; d < 32; d++) o[d] *= alpha;
    #pragma unroll
    for (int j = 0; j < 32; j++) {
      const float p = __expf(sc[j] - mrow);
      l += p;
      #pragma unroll
      for (int d = 0; d < 32; d++) o[d] = fmaf(p, Vs[j][seg + 4 * d], o[d]);
    }
  }

  const float inv = 1.f / l;
  float* dst = ctx + ((size_t)(b * NS + qrow)) * ND + h * NDH;
  #pragma unroll
  for (int d = 0; d < 32; d++) dst[seg + 4 * d] = o[d] * inv;
}

extern "C" void kernel_launch(void* const* d_in, const int* in_sizes, int n_in,
                              void* d_out, int out_size) {
  const float* x  = (const float*)d_in[0];
  const float* fc = (const float*)d_in[1];
  const float* fs = (const float*)d_in[2];
  // d_in[3] is the mask; causal handled analytically
  const float* wq = (const float*)d_in[4];
  const float* wk = (const float*)d_in[5];
  const float* wv = (const float*)d_in[6];
  const float* wo = (const float*)d_in[7];

  float *q, *k, *v, *ctx;
  cudaGetSymbolAddress((void**)&q,   g_q);
  cudaGetSymbolAddress((void**)&k,   g_k);
  cudaGetSymbolAddress((void**)&v,   g_v);
  cudaGetSymbolAddress((void**)&ctx, g_ctx);

  dim3 gg(ND / 128, NM / 128);
  gemm_nt<2><<<gg, 256>>>(x, wq, q, fc, fs);
  gemm_nt<2><<<gg, 256>>>(x, wk, k, fc, fs);
  gemm_nt<1><<<gg, 256>>>(x, wv, v, nullptr, nullptr);

  dim3 fg(NS / 64, NB * NH);
  flash_kernel<<<fg, 256>>>(q, k, v, ctx);

  gemm_nt<0><<<gg, 256>>>(ctx, wo, (float*)d_out, nullptr, nullptr);
}

// round 2
// speedup vs baseline: 1.3409x; 1.3409x over previous
#include <cuda_runtime.h>
#include <math.h>

#define NB 2
#define NS 2048
#define ND 2048
#define NH 16
#define NDH 128
#define NM (NB*NS)

// Scratch (device globals; no allocation allowed)
__device__ float g_q[(size_t)NB*NH*NS*NDH];
__device__ float g_k[(size_t)NB*NH*NS*NDH];
__device__ float g_v[(size_t)NB*NH*NS*NDH];
__device__ float g_ctx[(size_t)NB*NS*ND];

__device__ __forceinline__ unsigned f2tf(float f) {
  unsigned u;
  asm("cvt.rna.tf32.f32 %0, %1;" : "=r"(u) : "f"(f));
  return u;
}

// C[M,N] = A[M,K] * W[N,K]^T via mma.sync tf32.
// Block tile 128x128, K-tile 32, 256 threads = 8 warps (2x4), warp tile 64x32.
// Smem layout: [k][col] with XOR swizzle col = r ^ ((k&3)<<3) ^ (k&16):
// conflict-free for both transpose-stores and fragment loads.
// MODE 0: row-major store; MODE 1: head-layout scatter; MODE 2: + fused RoPE.
template<int MODE>
__global__ void __launch_bounds__(256) gemm_tc(
    const float* __restrict__ A, const float* __restrict__ W,
    float* __restrict__ C,
    const float* __restrict__ fcos, const float* __restrict__ fsin)
{
  __shared__ unsigned As[32 * 128];
  __shared__ unsigned Bs[32 * 128];
  const int K = ND;
  const int bm = blockIdx.y * 128;
  const int bn = blockIdx.x * 128;
  const int tid = threadIdx.x;
  const int warp = tid >> 5, lane = tid & 31;
  const int wm0 = (warp >> 2) * 64;   // warp M offset in tile
  const int wn0 = (warp & 3) * 32;    // warp N offset in tile
  const int g = lane >> 2, tk = lane & 3;

  float acc[4][4][4];
  #pragma unroll
  for (int mi = 0; mi < 4; mi++)
    #pragma unroll
    for (int ni = 0; ni < 4; ni++)
      #pragma unroll
      for (int c = 0; c < 4; c++) acc[mi][ni][c] = 0.f;

  const int r = tid >> 1;      // 0..127 (m or n row within tile)
  const int q = tid & 1;       // k half: 0 or 16
  const float* ap = A + (size_t)(bm + r) * K + q * 16;
  const float* wp = W + (size_t)(bn + r) * K + q * 16;

  float4 ra[4], rb[4];
  #pragma unroll
  for (int i = 0; i < 4; i++) {
    ra[i] = *(const float4*)(ap + 4 * i);
    rb[i] = *(const float4*)(wp + 4 * i);
  }

  const int niter = K / 32;
  for (int kt = 0; kt < niter; kt++) {
    // Store prefetched tile to smem (transposed, swizzled, tf32-rounded)
    #pragma unroll
    for (int i = 0; i < 4; i++) {
      const int kb = q * 16 + 4 * i;
      const float va[4] = {ra[i].x, ra[i].y, ra[i].z, ra[i].w};
      const float vb[4] = {rb[i].x, rb[i].y, rb[i].z, rb[i].w};
      #pragma unroll
      for (int c = 0; c < 4; c++) {
        const int k = kb + c;
        const int col = r ^ ((k & 3) << 3) ^ (k & 16);
        As[k * 128 + col] = f2tf(va[c]);
        Bs[k * 128 + col] = f2tf(vb[c]);
      }
    }
    __syncthreads();
    if (kt + 1 < niter) {
      ap += 32; wp += 32;
      #pragma unroll
      for (int i = 0; i < 4; i++) {
        ra[i] = *(const float4*)(ap + 4 * i);
        rb[i] = *(const float4*)(wp + 4 * i);
      }
    }
    // Compute: 4 k8-steps
    #pragma unroll
    for (int ks = 0; ks < 4; ks++) {
      const int k0 = ks * 8 + tk;        // rows for a0/a1/b0
      const int k1 = ks * 8 + 4 + tk;    // rows for a2/a3/b1
      const int sw0 = (tk << 3) ^ (k0 & 16);
      const int sw1 = (tk << 3) ^ (k1 & 16);
      unsigned afr[4][4], bfr[4][2];
      #pragma unroll
      for (int mi = 0; mi < 4; mi++) {
        const int m = wm0 + mi * 16 + g;
        afr[mi][0] = As[k0 * 128 + (m ^ sw0)];
        afr[mi][1] = As[k0 * 128 + ((m + 8) ^ sw0)];
        afr[mi][2] = As[k1 * 128 + (m ^ sw1)];
        afr[mi][3] = As[k1 * 128 + ((m + 8) ^ sw1)];
      }
      #pragma unroll
      for (int ni = 0; ni < 4; ni++) {
        const int n = wn0 + ni * 8 + g;
        bfr[ni][0] = Bs[k0 * 128 + (n ^ sw0)];
        bfr[ni][1] = Bs[k1 * 128 + (n ^ sw1)];
      }
      #pragma unroll
      for (int mi = 0; mi < 4; mi++)
        #pragma unroll
        for (int ni = 0; ni < 4; ni++) {
          asm volatile(
            "mma.sync.aligned.m16n8k8.row.col.f32.tf32.tf32.f32 "
            "{%0,%1,%2,%3},{%4,%5,%6,%7},{%8,%9},{%0,%1,%2,%3};\n"
            : "+f"(acc[mi][ni][0]), "+f"(acc[mi][ni][1]),
              "+f"(acc[mi][ni][2]), "+f"(acc[mi][ni][3])
            : "r"(afr[mi][0]), "r"(afr[mi][1]), "r"(afr[mi][2]), "r"(afr[mi][3]),
              "r"(bfr[ni][0]), "r"(bfr[ni][1]));
        }
    }
    __syncthreads();
  }

  // Epilogue. Accumulator c0,c1 are columns (2tk, 2tk+1): an even/odd pair,
  // which is exactly a RoPE rotation pair.
  #pragma unroll
  for (int mi = 0; mi < 4; mi++) {
    #pragma unroll
    for (int half = 0; half < 2; half++) {
      const int m = bm + wm0 + mi * 16 + g + half * 8;
      const int b = m / NS, s = m % NS;
      #pragma unroll
      for (int ni = 0; ni < 4; ni++) {
        const float v0 = acc[mi][ni][half * 2 + 0];
        const float v1 = acc[mi][ni][half * 2 + 1];
        const int n = bn + wn0 + ni * 8 + tk * 2;
        if (MODE == 0) {
          float2 vv = {v0, v1};
          *(float2*)&C[(size_t)m * ND + n] = vv;
        } else {
          const int h = n / NDH, d = n % NDH;
          float* dst = C + (((size_t)(b * NH + h)) * NS + s) * NDH;
          if (MODE == 1) {
            float2 vv = {v0, v1};
            *(float2*)&dst[d] = vv;
          } else {
            const int pi = d >> 1;
            const float cc = fcos[s * (NDH / 2) + pi];
            const float sn = fsin[s * (NDH / 2) + pi];
            float2 vv = {v0 * cc - v1 * sn, v0 * sn + v1 * cc};
            *(float2*)&dst[d] = vv;
          }
        }
      }
    }
  }
}

// Flash attention, causal, fp32 (unchanged from R1).
__global__ void __launch_bounds__(256) flash_kernel(
    const float* __restrict__ gq, const float* __restrict__ gk,
    const float* __restrict__ gv, float* __restrict__ ctx)
{
  const int bh = blockIdx.y;
  const int b = bh / NH, h = bh % NH;
  const int qbase = blockIdx.x * 64;
  const int tid = threadIdx.x;
  const int row = tid >> 2;
  const int seg = tid & 3;
  const int qrow = qbase + row;

  const float* qptr = gq + ((size_t)bh * NS + qrow) * NDH;
  float qr[32], o[32];
  #pragma unroll
  for (int d = 0; d < 32; d++) {
    qr[d] = qptr[seg + 4 * d];
    o[d] = 0.f;
  }
  float mrow = -1e30f, l = 0.f;

  __shared__ float Ks[32][128];
  __shared__ float Vs[32][128];
  const float* kbp = gk + (size_t)bh * NS * NDH;
  const float* vbp = gv + (size_t)bh * NS * NDH;
  const int ntiles = qbase / 32 + 2;
  const float scale = 0.08838834764831845f;  // 1/sqrt(128)

  for (int t = 0; t < ntiles; t++) {
    const int k0 = t * 32;
    __syncthreads();
    const float4* ksrc = (const float4*)(kbp + (size_t)k0 * NDH);
    const float4* vsrc = (const float4*)(vbp + (size_t)k0 * NDH);
    float4* kdst = (float4*)&Ks[0][0];
    float4* vdst = (float4*)&Vs[0][0];
    #pragma unroll
    for (int i = 0; i < 4; i++) {
      kdst[tid + 256 * i] = ksrc[tid + 256 * i];
      vdst[tid + 256 * i] = vsrc[tid + 256 * i];
    }
    __syncthreads();

    float sc[32];
    #pragma unroll
    for (int j = 0; j < 32; j++) {
      float s = 0.f;
      #pragma unroll
      for (int d = 0; d < 32; d++) s = fmaf(qr[d], Ks[j][seg + 4 * d], s);
      s += __shfl_xor_sync(0xffffffffu, s, 1);
      s += __shfl_xor_sync(0xffffffffu, s, 2);
      sc[j] = (k0 + j <= qrow) ? s * scale : -1e30f;
    }
    float mt = mrow;
    #pragma unroll
    for (int j = 0; j < 32; j++) mt = fmaxf(mt, sc[j]);
    const float alpha = __expf(mrow - mt);
    mrow = mt;
    l *= alpha;
    #pragma unroll
    for (int d = 0; d < 32; d++) o[d] *= alpha;
    #pragma unroll
    for (int j = 0; j < 32; j++) {
      const float p = __expf(sc[j] - mrow);
      l += p;
      #pragma unroll
      for (int d = 0; d < 32; d++) o[d] = fmaf(p, Vs[j][seg + 4 * d], o[d]);
    }
  }

  const float inv = 1.f / l;
  float* dst = ctx + ((size_t)(b * NS + qrow)) * ND + h * NDH;
  #pragma unroll
  for (int d = 0; d < 32; d++) dst[seg + 4 * d] = o[d] * inv;
}

extern "C" void kernel_launch(void* const* d_in, const int* in_sizes, int n_in,
                              void* d_out, int out_size) {
  const float* x  = (const float*)d_in[0];
  const float* fc = (const float*)d_in[1];
  const float* fs = (const float*)d_in[2];
  // d_in[3] is the mask; causal handled analytically
  const float* wq = (const float*)d_in[4];
  const float* wk = (const float*)d_in[5];
  const float* wv = (const float*)d_in[6];
  const float* wo = (const float*)d_in[7];

  float *q, *k, *v, *ctx;
  cudaGetSymbolAddress((void**)&q,   g_q);
  cudaGetSymbolAddress((void**)&k,   g_k);
  cudaGetSymbolAddress((void**)&v,   g_v);
  cudaGetSymbolAddress((void**)&ctx, g_ctx);

  dim3 gg(ND / 128, NM / 128);
  gemm_tc<2><<<gg, 256>>>(x, wq, q, fc, fs);
  gemm_tc<2><<<gg, 256>>>(x, wk, k, fc, fs);
  gemm_tc<1><<<gg, 256>>>(x, wv, v, nullptr, nullptr);

  dim3 fg(NS / 64, NB * NH);
  flash_kernel<<<fg, 256>>>(q, k, v, ctx);

  gemm_tc<0><<<gg, 256>>>(ctx, wo, (float*)d_out, nullptr, nullptr);
}

// round 3
// speedup vs baseline: 4.7758x; 3.5616x over previous
#include <cuda_runtime.h>
#include <cuda_fp16.h>
#include <math.h>

#define NB 2
#define NS 2048
#define ND 2048
#define NH 16
#define NDH 128
#define NM (NB*NS)

// Scratch (device globals; no allocation allowed)
__device__ float g_q[(size_t)NB*NH*NS*NDH];
__device__ float g_k[(size_t)NB*NH*NS*NDH];
__device__ __half g_vt[(size_t)NB*NH*NDH*NS];   // V transposed: [b,h,dh,s] fp16
__device__ float g_ctx[(size_t)NB*NS*ND];

__device__ __forceinline__ unsigned f2tf(float f) {
  unsigned u;
  asm("cvt.rna.tf32.f32 %0, %1;" : "=r"(u) : "f"(f));
  return u;
}
__device__ __forceinline__ unsigned packh2(float lo, float hi) {
  __half2 h = __floats2half2_rn(lo, hi);
  return *(unsigned*)&h;
}
__device__ __forceinline__ void mma_tf32(float* c, unsigned a0, unsigned a1,
                                         unsigned a2, unsigned a3,
                                         unsigned b0, unsigned b1) {
  asm volatile(
    "mma.sync.aligned.m16n8k8.row.col.f32.tf32.tf32.f32 "
    "{%0,%1,%2,%3},{%4,%5,%6,%7},{%8,%9},{%0,%1,%2,%3};\n"
    : "+f"(c[0]), "+f"(c[1]), "+f"(c[2]), "+f"(c[3])
    : "r"(a0), "r"(a1), "r"(a2), "r"(a3), "r"(b0), "r"(b1));
}
__device__ __forceinline__ void mma_f16(float* c, unsigned a0, unsigned a1,
                                        unsigned a2, unsigned a3,
                                        unsigned b0, unsigned b1) {
  asm volatile(
    "mma.sync.aligned.m16n8k16.row.col.f32.f16.f16.f32 "
    "{%0,%1,%2,%3},{%4,%5,%6,%7},{%8,%9},{%0,%1,%2,%3};\n"
    : "+f"(c[0]), "+f"(c[1]), "+f"(c[2]), "+f"(c[3])
    : "r"(a0), "r"(a1), "r"(a2), "r"(a3), "r"(b0), "r"(b1));
}

// ============================================================================
// GEMM: C[M,N] = A[M,K] * W[N,K]^T via mma.sync tf32 (as in R2).
// MODE 0: row-major; MODE 1: head scatter; MODE 2: + RoPE; MODE 3: fp16
// transposed scatter [b,h,dh,s] into Ct.
// ============================================================================
template<int MODE>
__global__ void __launch_bounds__(256) gemm_tc(
    const float* __restrict__ A, const float* __restrict__ W,
    float* __restrict__ C, __half* __restrict__ Ct,
    const float* __restrict__ fcos, const float* __restrict__ fsin)
{
  __shared__ unsigned As[32 * 128];
  __shared__ unsigned Bs[32 * 128];
  const int K = ND;
  const int bm = blockIdx.y * 128;
  const int bn = blockIdx.x * 128;
  const int tid = threadIdx.x;
  const int warp = tid >> 5, lane = tid & 31;
  const int wm0 = (warp >> 2) * 64;
  const int wn0 = (warp & 3) * 32;
  const int g = lane >> 2, tk = lane & 3;

  float acc[4][4][4];
  #pragma unroll
  for (int mi = 0; mi < 4; mi++)
    #pragma unroll
    for (int ni = 0; ni < 4; ni++)
      #pragma unroll
      for (int c = 0; c < 4; c++) acc[mi][ni][c] = 0.f;

  const int r = tid >> 1;
  const int q = tid & 1;
  const float* ap = A + (size_t)(bm + r) * K + q * 16;
  const float* wp = W + (size_t)(bn + r) * K + q * 16;

  float4 ra[4], rb[4];
  #pragma unroll
  for (int i = 0; i < 4; i++) {
    ra[i] = *(const float4*)(ap + 4 * i);
    rb[i] = *(const float4*)(wp + 4 * i);
  }

  const int niter = K / 32;
  for (int kt = 0; kt < niter; kt++) {
    #pragma unroll
    for (int i = 0; i < 4; i++) {
      const int kb = q * 16 + 4 * i;
      const float va[4] = {ra[i].x, ra[i].y, ra[i].z, ra[i].w};
      const float vb[4] = {rb[i].x, rb[i].y, rb[i].z, rb[i].w};
      #pragma unroll
      for (int c = 0; c < 4; c++) {
        const int k = kb + c;
        const int col = r ^ ((k & 3) << 3) ^ (k & 16);
        As[k * 128 + col] = f2tf(va[c]);
        Bs[k * 128 + col] = f2tf(vb[c]);
      }
    }
    __syncthreads();
    if (kt + 1 < niter) {
      ap += 32; wp += 32;
      #pragma unroll
      for (int i = 0; i < 4; i++) {
        ra[i] = *(const float4*)(ap + 4 * i);
        rb[i] = *(const float4*)(wp + 4 * i);
      }
    }
    #pragma unroll
    for (int ks = 0; ks < 4; ks++) {
      const int k0 = ks * 8 + tk;
      const int k1 = ks * 8 + 4 + tk;
      const int sw0 = (tk << 3) ^ (k0 & 16);
      const int sw1 = (tk << 3) ^ (k1 & 16);
      unsigned afr[4][4], bfr[4][2];
      #pragma unroll
      for (int mi = 0; mi < 4; mi++) {
        const int m = wm0 + mi * 16 + g;
        afr[mi][0] = As[k0 * 128 + (m ^ sw0)];
        afr[mi][1] = As[k0 * 128 + ((m + 8) ^ sw0)];
        afr[mi][2] = As[k1 * 128 + (m ^ sw1)];
        afr[mi][3] = As[k1 * 128 + ((m + 8) ^ sw1)];
      }
      #pragma unroll
      for (int ni = 0; ni < 4; ni++) {
        const int n = wn0 + ni * 8 + g;
        bfr[ni][0] = Bs[k0 * 128 + (n ^ sw0)];
        bfr[ni][1] = Bs[k1 * 128 + (n ^ sw1)];
      }
      #pragma unroll
      for (int mi = 0; mi < 4; mi++)
        #pragma unroll
        for (int ni = 0; ni < 4; ni++)
          mma_tf32(acc[mi][ni], afr[mi][0], afr[mi][1], afr[mi][2], afr[mi][3],
                   bfr[ni][0], bfr[ni][1]);
    }
    __syncthreads();
  }

  #pragma unroll
  for (int mi = 0; mi < 4; mi++) {
    #pragma unroll
    for (int half = 0; half < 2; half++) {
      const int m = bm + wm0 + mi * 16 + g + half * 8;
      const int b = m / NS, s = m % NS;
      #pragma unroll
      for (int ni = 0; ni < 4; ni++) {
        const float v0 = acc[mi][ni][half * 2 + 0];
        const float v1 = acc[mi][ni][half * 2 + 1];
        const int n = bn + wn0 + ni * 8 + tk * 2;
        if (MODE == 0) {
          float2 vv = {v0, v1};
          *(float2*)&C[(size_t)m * ND + n] = vv;
        } else if (MODE == 3) {
          const int h = n / NDH, d = n % NDH;
          __half* dst = Ct + (((size_t)(b * NH + h)) * NDH + d) * NS + s;
          dst[0]  = __float2half_rn(v0);
          dst[NS] = __float2half_rn(v1);
        } else {
          const int h = n / NDH, d = n % NDH;
          float* dst = C + (((size_t)(b * NH + h)) * NS + s) * NDH;
          if (MODE == 1) {
            float2 vv = {v0, v1};
            *(float2*)&dst[d] = vv;
          } else {
            const int pi = d >> 1;
            const float cc = fcos[s * (NDH / 2) + pi];
            const float sn = fsin[s * (NDH / 2) + pi];
            float2 vv = {v0 * cc - v1 * sn, v0 * sn + v1 * cc};
            *(float2*)&dst[d] = vv;
          }
        }
      }
    }
  }
}

// ============================================================================
// Flash attention (causal) on tensor cores.
// Br=128 (8 warps x 16 rows), Bc=64. S = Q*K^T in tf32 mma; O^T = V^T * P^T
// in fp16 mma (P^T is register-direct from the S accumulator layout).
// Smem: Qs[128][132] tf32, Ks[64][132] tf32, Vt[128][72] fp16 (36 uints/row).
// ============================================================================
#define FL_QPITCH 132
#define FL_VPITCH 36
#define FL_SMEM ((128*FL_QPITCH + 64*FL_QPITCH + 128*FL_VPITCH) * 4)

__global__ void __launch_bounds__(256) flash_tc(
    const float* __restrict__ gq, const float* __restrict__ gk,
    const __half* __restrict__ gvt, float* __restrict__ ctx)
{
  extern __shared__ unsigned sm[];
  unsigned* Qs = sm;                                  // [128][132]
  unsigned* Ks = sm + 128 * FL_QPITCH;                // [64][132]
  unsigned* Vt = sm + 128 * FL_QPITCH + 64 * FL_QPITCH; // [128][36] (half2)

  const int bh = blockIdx.y;
  const int b = bh >> 4, h = bh & 15;
  const int qb = blockIdx.x * 128;
  const int tid = threadIdx.x;
  const int warp = tid >> 5, lane = tid & 31;
  const int g = lane >> 2, tk = lane & 3;
  const int m0 = warp * 16;
  const int qrow_max = qb + m0 + 15;
  const float scale = 0.08838834764831845f;  // 1/sqrt(128)

  // Load Q tile (scale folded in)
  const float* qbase = gq + ((size_t)bh * NS + qb) * NDH;
  #pragma unroll
  for (int i = 0; i < 16; i++) {
    int idx = i * 256 + tid;
    int row = idx >> 5, c4 = idx & 31;
    float4 v = *(const float4*)(qbase + row * NDH + c4 * 4);
    unsigned* dst = Qs + row * FL_QPITCH + c4 * 4;
    uint4 u = {f2tf(v.x * scale), f2tf(v.y * scale),
               f2tf(v.z * scale), f2tf(v.w * scale)};
    *(uint4*)dst = u;
  }

  float oacc[8][2][4];
  #pragma unroll
  for (int mi = 0; mi < 8; mi++)
    #pragma unroll
    for (int nt = 0; nt < 2; nt++)
      #pragma unroll
      for (int c = 0; c < 4; c++) oacc[mi][nt][c] = 0.f;
  float mrow0 = -1e30f, mrow1 = -1e30f, lrow0 = 0.f, lrow1 = 0.f;

  const float* kbase = gk + (size_t)bh * NS * NDH;
  const unsigned* vtbase = (const unsigned*)(gvt + (size_t)bh * NDH * NS);
  const int ntiles = qb / 64 + 2;
  __syncthreads();

  for (int t = 0; t < ntiles; t++) {
    const int k0 = t * 64;
    __syncthreads();
    // K tile: 64x128 f32 -> tf32
    #pragma unroll
    for (int i = 0; i < 8; i++) {
      int idx = i * 256 + tid;
      int row = idx >> 5, c4 = idx & 31;
      float4 v = *(const float4*)(kbase + (size_t)(k0 + row) * NDH + c4 * 4);
      uint4 u = {f2tf(v.x), f2tf(v.y), f2tf(v.z), f2tf(v.w)};
      *(uint4*)(Ks + row * FL_QPITCH + c4 * 4) = u;
    }
    // Vt tile: 128 rows x 32 uints (64 halves)
    #pragma unroll
    for (int i = 0; i < 16; i++) {
      int idx = i * 256 + tid;
      int row = idx >> 5, cu = idx & 31;
      Vt[row * FL_VPITCH + cu] = vtbase[(size_t)row * (NS / 2) + k0 / 2 + cu];
    }
    __syncthreads();
    if (k0 > qrow_max) continue;

    // ---- S = Q K^T (tf32) ----
    float sacc[8][4];
    #pragma unroll
    for (int nt = 0; nt < 8; nt++)
      #pragma unroll
      for (int c = 0; c < 4; c++) sacc[nt][c] = 0.f;

    #pragma unroll
    for (int ks = 0; ks < 16; ks++) {
      const int kk = ks * 8;
      const unsigned* qr0 = Qs + (m0 + g) * FL_QPITCH + kk + tk;
      const unsigned* qr1 = Qs + (m0 + 8 + g) * FL_QPITCH + kk + tk;
      unsigned a0 = qr0[0], a1 = qr1[0], a2 = qr0[4], a3 = qr1[4];
      #pragma unroll
      for (int nt = 0; nt < 8; nt++) {
        const unsigned* kr = Ks + (nt * 8 + g) * FL_QPITCH + kk + tk;
        mma_tf32(sacc[nt], a0, a1, a2, a3, kr[0], kr[4]);
      }
    }

    // ---- mask (only near diagonal) ----
    if (k0 + 63 > qb + m0) {
      const int r0 = qb + m0 + g, r1 = r0 + 8;
      #pragma unroll
      for (int nt = 0; nt < 8; nt++) {
        const int key0 = k0 + nt * 8 + 2 * tk;
        if (key0     > r0) sacc[nt][0] = -1e30f;
        if (key0 + 1 > r0) sacc[nt][1] = -1e30f;
        if (key0     > r1) sacc[nt][2] = -1e30f;
        if (key0 + 1 > r1) sacc[nt][3] = -1e30f;
      }
    }

    // ---- online softmax ----
    float mx0 = mrow0, mx1 = mrow1;
    #pragma unroll
    for (int nt = 0; nt < 8; nt++) {
      mx0 = fmaxf(mx0, fmaxf(sacc[nt][0], sacc[nt][1]));
      mx1 = fmaxf(mx1, fmaxf(sacc[nt][2], sacc[nt][3]));
    }
    mx0 = fmaxf(mx0, __shfl_xor_sync(0xffffffffu, mx0, 1));
    mx0 = fmaxf(mx0, __shfl_xor_sync(0xffffffffu, mx0, 2));
    mx1 = fmaxf(mx1, __shfl_xor_sync(0xffffffffu, mx1, 1));
    mx1 = fmaxf(mx1, __shfl_xor_sync(0xffffffffu, mx1, 2));
    const float al0 = __expf(mrow0 - mx0);
    const float al1 = __expf(mrow1 - mx1);
    mrow0 = mx0; mrow1 = mx1;
    lrow0 *= al0; lrow1 *= al1;

    const float af00 = __shfl_sync(0xffffffffu, al0, 8 * tk);
    const float af01 = __shfl_sync(0xffffffffu, al0, 8 * tk + 4);
    const float af10 = __shfl_sync(0xffffffffu, al1, 8 * tk);
    const float af11 = __shfl_sync(0xffffffffu, al1, 8 * tk + 4);
    #pragma unroll
    for (int mi = 0; mi < 8; mi++) {
      oacc[mi][0][0] *= af00; oacc[mi][0][1] *= af01;
      oacc[mi][0][2] *= af00; oacc[mi][0][3] *= af01;
      oacc[mi][1][0] *= af10; oacc[mi][1][1] *= af11;
      oacc[mi][1][2] *= af10; oacc[mi][1][3] *= af11;
    }

    float cb0 = 0.f, cb1 = 0.f;
    #pragma unroll
    for (int nt = 0; nt < 8; nt++) {
      sacc[nt][0] = __expf(sacc[nt][0] - mx0);
      sacc[nt][1] = __expf(sacc[nt][1] - mx0);
      sacc[nt][2] = __expf(sacc[nt][2] - mx1);
      sacc[nt][3] = __expf(sacc[nt][3] - mx1);
      cb0 += sacc[nt][0] + sacc[nt][1];
      cb1 += sacc[nt][2] + sacc[nt][3];
    }
    cb0 += __shfl_xor_sync(0xffffffffu, cb0, 1);
    cb0 += __shfl_xor_sync(0xffffffffu, cb0, 2);
    cb1 += __shfl_xor_sync(0xffffffffu, cb1, 1);
    cb1 += __shfl_xor_sync(0xffffffffu, cb1, 2);
    lrow0 += cb0; lrow1 += cb1;

    // ---- O^T += V^T * P^T (fp16); P^T fragments direct from sacc ----
    #pragma unroll
    for (int ks = 0; ks < 4; ks++) {
      const unsigned bl0 = packh2(sacc[2 * ks][0],     sacc[2 * ks][1]);
      const unsigned bl1 = packh2(sacc[2 * ks + 1][0], sacc[2 * ks + 1][1]);
      const unsigned bh0 = packh2(sacc[2 * ks][2],     sacc[2 * ks][3]);
      const unsigned bh1 = packh2(sacc[2 * ks + 1][2], sacc[2 * ks + 1][3]);
      #pragma unroll
      for (int mi = 0; mi < 8; mi++) {
        const unsigned* vr0 = Vt + (mi * 16 + g) * FL_VPITCH + ks * 8 + tk;
        const unsigned* vr1 = vr0 + 8 * FL_VPITCH;
        const unsigned va0 = vr0[0], va1 = vr1[0], va2 = vr0[4], va3 = vr1[4];
        mma_f16(oacc[mi][0], va0, va1, va2, va3, bl0, bl1);
        mma_f16(oacc[mi][1], va0, va1, va2, va3, bh0, bh1);
      }
    }
  }

  // ---- normalize + store (O^T layout: m=dh, n=qrow) ----
  const float l00 = __shfl_sync(0xffffffffu, lrow0, 8 * tk);
  const float l01 = __shfl_sync(0xffffffffu, lrow0, 8 * tk + 4);
  const float l10 = __shfl_sync(0xffffffffu, lrow1, 8 * tk);
  const float l11 = __shfl_sync(0xffffffffu, lrow1, 8 * tk + 4);
  const float i00 = 1.f / l00, i01 = 1.f / l01;
  const float i10 = 1.f / l10, i11 = 1.f / l11;

  float* cp = ctx + ((size_t)(b * NS + qb + m0)) * ND + h * NDH;
  #pragma unroll
  for (int mi = 0; mi < 8; mi++) {
    const int d0 = mi * 16 + g;
    cp[(size_t)(2 * tk) * ND + d0]         = oacc[mi][0][0] * i00;
    cp[(size_t)(2 * tk + 1) * ND + d0]     = oacc[mi][0][1] * i01;
    cp[(size_t)(2 * tk) * ND + d0 + 8]     = oacc[mi][0][2] * i00;
    cp[(size_t)(2 * tk + 1) * ND + d0 + 8] = oacc[mi][0][3] * i01;
    cp[(size_t)(8 + 2 * tk) * ND + d0]         = oacc[mi][1][0] * i10;
    cp[(size_t)(9 + 2 * tk) * ND + d0]         = oacc[mi][1][1] * i11;
    cp[(size_t)(8 + 2 * tk) * ND + d0 + 8]     = oacc[mi][1][2] * i10;
    cp[(size_t)(9 + 2 * tk) * ND + d0 + 8]     = oacc[mi][1][3] * i11;
  }
}

extern "C" void kernel_launch(void* const* d_in, const int* in_sizes, int n_in,
                              void* d_out, int out_size) {
  const float* x  = (const float*)d_in[0];
  const float* fc = (const float*)d_in[1];
  const float* fs = (const float*)d_in[2];
  // d_in[3] is the mask; causal handled analytically
  const float* wq = (const float*)d_in[4];
  const float* wk = (const float*)d_in[5];
  const float* wv = (const float*)d_in[6];
  const float* wo = (const float*)d_in[7];

  float *q, *k, *ctx;
  __half* vt;
  cudaGetSymbolAddress((void**)&q,   g_q);
  cudaGetSymbolAddress((void**)&k,   g_k);
  cudaGetSymbolAddress((void**)&vt,  g_vt);
  cudaGetSymbolAddress((void**)&ctx, g_ctx);

  cudaFuncSetAttribute(flash_tc, cudaFuncAttributeMaxDynamicSharedMemorySize,
                       FL_SMEM);

  dim3 gg(ND / 128, NM / 128);
  gemm_tc<2><<<gg, 256>>>(x, wq, q, nullptr, fc, fs);
  gemm_tc<2><<<gg, 256>>>(x, wk, k, nullptr, fc, fs);
  gemm_tc<3><<<gg, 256>>>(x, wv, nullptr, vt, nullptr, nullptr);

  dim3 fg(NS / 128, NB * NH);
  flash_tc<<<fg, 256, FL_SMEM>>>(q, k, vt, ctx);

  gemm_tc<0><<<gg, 256>>>(ctx, wo, (float*)d_out, nullptr, nullptr, nullptr);
}

// round 4
// speedup vs baseline: 7.9198x; 1.6583x over previous
#include <cuda_runtime.h>
#include <cuda_fp16.h>
#include <math.h>

#define NB 2
#define NS 2048
#define ND 2048
#define NH 16
#define NDH 128
#define NM (NB*NS)

// Scratch (device globals; no allocation allowed)
__device__ float g_q[(size_t)NB*NH*NS*NDH];
__device__ float g_k[(size_t)NB*NH*NS*NDH];
__device__ __half g_vt[(size_t)NB*NH*NDH*NS];   // V transposed: [b,h,dh,s] fp16
__device__ float g_ctx[(size_t)NB*NS*ND];
__device__ float g_xt[(size_t)NM*ND];           // x rounded to tf32
__device__ float g_wqt[(size_t)ND*ND];
__device__ float g_wkt[(size_t)ND*ND];
__device__ float g_wvt[(size_t)ND*ND];
__device__ float g_wot[(size_t)ND*ND];

__device__ __forceinline__ unsigned f2tf(float f) {
  unsigned u;
  asm("cvt.rna.tf32.f32 %0, %1;" : "=r"(u) : "f"(f));
  return u;
}
__device__ __forceinline__ unsigned packh2(float lo, float hi) {
  __half2 h = __floats2half2_rn(lo, hi);
  return *(unsigned*)&h;
}
__device__ __forceinline__ void mma_tf32(float* c, unsigned a0, unsigned a1,
                                         unsigned a2, unsigned a3,
                                         unsigned b0, unsigned b1) {
  asm volatile(
    "mma.sync.aligned.m16n8k8.row.col.f32.tf32.tf32.f32 "
    "{%0,%1,%2,%3},{%4,%5,%6,%7},{%8,%9},{%0,%1,%2,%3};\n"
    : "+f"(c[0]), "+f"(c[1]), "+f"(c[2]), "+f"(c[3])
    : "r"(a0), "r"(a1), "r"(a2), "r"(a3), "r"(b0), "r"(b1));
}
__device__ __forceinline__ void mma_f16(float* c, unsigned a0, unsigned a1,
                                        unsigned a2, unsigned a3,
                                        unsigned b0, unsigned b1) {
  asm volatile(
    "mma.sync.aligned.m16n8k16.row.col.f32.f16.f16.f32 "
    "{%0,%1,%2,%3},{%4,%5,%6,%7},{%8,%9},{%0,%1,%2,%3};\n"
    : "+f"(c[0]), "+f"(c[1]), "+f"(c[2]), "+f"(c[3])
    : "r"(a0), "r"(a1), "r"(a2), "r"(a3), "r"(b0), "r"(b1));
}

// Round fp32 -> tf32-in-fp32 (RNA), vectorized.
__global__ void round_tf32_k(const float* __restrict__ src,
                             float* __restrict__ dst, int n4) {
  int i = blockIdx.x * 256 + threadIdx.x;
  if (i < n4) {
    float4 v = ((const float4*)src)[i];
    uint4 u = {f2tf(v.x), f2tf(v.y), f2tf(v.z), f2tf(v.w)};
    ((uint4*)dst)[i] = u;
  }
}

// ============================================================================
// GEMM: C[M,N] = A[M,K] * W[N,K]^T, tf32 mma.sync, cp.async 3-stage pipeline.
// Inputs must already be tf32-rounded fp32. Block 128x128, K-tile 32,
// 256 threads = 8 warps (2x4), warp tile 64x32.
// Smem per tile: [row][k] fp32, float4-chunk XOR swizzle (chunk ^= row&7).
// MODE 0: row-major store; MODE 2: head scatter + RoPE; MODE 3: fp16
// transposed scatter [b,h,dh,s].
// ============================================================================
#define GM_SMEM (3 * 4096 * 2 * 4)

template<int MODE>
__global__ void __launch_bounds__(256, 2) gemm_tc(
    const float* __restrict__ A, const float* __restrict__ W,
    float* __restrict__ C, __half* __restrict__ Ct,
    const float* __restrict__ fcos, const float* __restrict__ fsin)
{
  extern __shared__ float sms[];
  float* As = sms;                 // [3][128*32]
  float* Bs = sms + 3 * 4096;      // [3][128*32]
  const int K = ND;
  const int bm = blockIdx.y * 128;
  const int bn = blockIdx.x * 128;
  const int tid = threadIdx.x;
  const int warp = tid >> 5, lane = tid & 31;
  const int wm0 = (warp >> 2) * 64;
  const int wn0 = (warp & 3) * 32;
  const int g = lane >> 2, tk = lane & 3;

  // copy mapping: thread handles rows r0+32i, chunk c (16B) of each row
  const int c = tid & 7;
  const int r0 = tid >> 3;
  const int csw = c ^ (r0 & 7);   // (r0+32i)&7 == r0&7
  const unsigned sa0 = (unsigned)__cvta_generic_to_shared(As) + (r0 * 32 + csw * 4) * 4;
  const unsigned sb0 = (unsigned)__cvta_generic_to_shared(Bs) + (r0 * 32 + csw * 4) * 4;
  const float* ga0 = A + (size_t)(bm + r0) * K + c * 4;
  const float* gw0 = W + (size_t)(bn + r0) * K + c * 4;

  float acc[4][4][4];
  #pragma unroll
  for (int mi = 0; mi < 4; mi++)
    #pragma unroll
    for (int ni = 0; ni < 4; ni++)
      #pragma unroll
      for (int cc = 0; cc < 4; cc++) acc[mi][ni][cc] = 0.f;

  #define GM_ISSUE(kt, st) do { \
    const float* _ga = ga0 + (kt) * 32; \
    const float* _gw = gw0 + (kt) * 32; \
    const unsigned _da = sa0 + (st) * 4096 * 4; \
    const unsigned _db = sb0 + (st) * 4096 * 4; \
    _Pragma("unroll") \
    for (int i = 0; i < 4; i++) { \
      asm volatile("cp.async.cg.shared.global [%0], [%1], 16;\n" \
                   :: "r"(_da + i * 32 * 32 * 4), "l"(_ga + (size_t)32 * i * K)); \
      asm volatile("cp.async.cg.shared.global [%0], [%1], 16;\n" \
                   :: "r"(_db + i * 32 * 32 * 4), "l"(_gw + (size_t)32 * i * K)); \
    } \
  } while (0)

  GM_ISSUE(0, 0);
  asm volatile("cp.async.commit_group;\n" ::);
  GM_ISSUE(1, 1);
  asm volatile("cp.async.commit_group;\n" ::);

  const int niter = K / 32;   // 64
  int st_c = 0, st_p = 2;
  for (int kt = 0; kt < niter; kt++) {
    asm volatile("cp.async.wait_group 1;\n" ::);
    __syncthreads();
    if (kt + 2 < niter) GM_ISSUE(kt + 2, st_p);
    asm volatile("cp.async.commit_group;\n" ::);

    const float* a = As + st_c * 4096;
    const float* b = Bs + st_c * 4096;
    #pragma unroll
    for (int ks = 0; ks < 4; ks++) {
      const int col0 = ((2 * ks) ^ g) * 4 + tk;
      const int col1 = ((2 * ks + 1) ^ g) * 4 + tk;
      unsigned afr[4][4], bfr[4][2];
      #pragma unroll
      for (int mi = 0; mi < 4; mi++) {
        const int m = wm0 + mi * 16 + g;
        afr[mi][0] = __float_as_uint(a[m * 32 + col0]);
        afr[mi][1] = __float_as_uint(a[(m + 8) * 32 + col0]);
        afr[mi][2] = __float_as_uint(a[m * 32 + col1]);
        afr[mi][3] = __float_as_uint(a[(m + 8) * 32 + col1]);
      }
      #pragma unroll
      for (int ni = 0; ni < 4; ni++) {
        const int n = wn0 + ni * 8 + g;
        bfr[ni][0] = __float_as_uint(b[n * 32 + col0]);
        bfr[ni][1] = __float_as_uint(b[n * 32 + col1]);
      }
      #pragma unroll
      for (int mi = 0; mi < 4; mi++)
        #pragma unroll
        for (int ni = 0; ni < 4; ni++)
          mma_tf32(acc[mi][ni], afr[mi][0], afr[mi][1], afr[mi][2], afr[mi][3],
                   bfr[ni][0], bfr[ni][1]);
    }
    st_c = (st_c == 2) ? 0 : st_c + 1;
    st_p = (st_p == 2) ? 0 : st_p + 1;
    __syncthreads();
  }

  #pragma unroll
  for (int mi = 0; mi < 4; mi++) {
    #pragma unroll
    for (int half = 0; half < 2; half++) {
      const int m = bm + wm0 + mi * 16 + g + half * 8;
      const int b = m / NS, s = m % NS;
      #pragma unroll
      for (int ni = 0; ni < 4; ni++) {
        const float v0 = acc[mi][ni][half * 2 + 0];
        const float v1 = acc[mi][ni][half * 2 + 1];
        const int n = bn + wn0 + ni * 8 + tk * 2;
        if (MODE == 0) {
          float2 vv = {v0, v1};
          *(float2*)&C[(size_t)m * ND + n] = vv;
        } else if (MODE == 3) {
          const int h = n / NDH, d = n % NDH;
          __half* dst = Ct + (((size_t)(b * NH + h)) * NDH + d) * NS + s;
          dst[0]  = __float2half_rn(v0);
          dst[NS] = __float2half_rn(v1);
        } else {
          const int h = n / NDH, d = n % NDH;
          float* dst = C + (((size_t)(b * NH + h)) * NS + s) * NDH;
          const int pi = d >> 1;
          const float cc = fcos[s * (NDH / 2) + pi];
          const float sn = fsin[s * (NDH / 2) + pi];
          float2 vv = {v0 * cc - v1 * sn, v0 * sn + v1 * cc};
          *(float2*)&dst[d] = vv;
        }
      }
    }
  }
}

// ============================================================================
// Flash attention (causal) on tensor cores (as R3; ctx stores tf32-rounded).
// ============================================================================
#define FL_QPITCH 132
#define FL_VPITCH 36
#define FL_SMEM ((128*FL_QPITCH + 64*FL_QPITCH + 128*FL_VPITCH) * 4)

__global__ void __launch_bounds__(256) flash_tc(
    const float* __restrict__ gq, const float* __restrict__ gk,
    const __half* __restrict__ gvt, float* __restrict__ ctx)
{
  extern __shared__ unsigned sm[];
  unsigned* Qs = sm;                                  // [128][132]
  unsigned* Ks = sm + 128 * FL_QPITCH;                // [64][132]
  unsigned* Vt = sm + 128 * FL_QPITCH + 64 * FL_QPITCH; // [128][36] (half2)

  const int bh = blockIdx.y;
  const int b = bh >> 4, h = bh & 15;
  const int qb = blockIdx.x * 128;
  const int tid = threadIdx.x;
  const int warp = tid >> 5, lane = tid & 31;
  const int g = lane >> 2, tk = lane & 3;
  const int m0 = warp * 16;
  const int qrow_max = qb + m0 + 15;
  const float scale = 0.08838834764831845f;  // 1/sqrt(128)

  const float* qbase = gq + ((size_t)bh * NS + qb) * NDH;
  #pragma unroll
  for (int i = 0; i < 16; i++) {
    int idx = i * 256 + tid;
    int row = idx >> 5, c4 = idx & 31;
    float4 v = *(const float4*)(qbase + row * NDH + c4 * 4);
    unsigned* dst = Qs + row * FL_QPITCH + c4 * 4;
    uint4 u = {f2tf(v.x * scale), f2tf(v.y * scale),
               f2tf(v.z * scale), f2tf(v.w * scale)};
    *(uint4*)dst = u;
  }

  float oacc[8][2][4];
  #pragma unroll
  for (int mi = 0; mi < 8; mi++)
    #pragma unroll
    for (int nt = 0; nt < 2; nt++)
      #pragma unroll
      for (int c = 0; c < 4; c++) oacc[mi][nt][c] = 0.f;
  float mrow0 = -1e30f, mrow1 = -1e30f, lrow0 = 0.f, lrow1 = 0.f;

  const float* kbase = gk + (size_t)bh * NS * NDH;
  const unsigned* vtbase = (const unsigned*)(gvt + (size_t)bh * NDH * NS);
  const int ntiles = qb / 64 + 2;
  __syncthreads();

  for (int t = 0; t < ntiles; t++) {
    const int k0 = t * 64;
    __syncthreads();
    #pragma unroll
    for (int i = 0; i < 8; i++) {
      int idx = i * 256 + tid;
      int row = idx >> 5, c4 = idx & 31;
      float4 v = *(const float4*)(kbase + (size_t)(k0 + row) * NDH + c4 * 4);
      uint4 u = {f2tf(v.x), f2tf(v.y), f2tf(v.z), f2tf(v.w)};
      *(uint4*)(Ks + row * FL_QPITCH + c4 * 4) = u;
    }
    #pragma unroll
    for (int i = 0; i < 16; i++) {
      int idx = i * 256 + tid;
      int row = idx >> 5, cu = idx & 31;
      Vt[row * FL_VPITCH + cu] = vtbase[(size_t)row * (NS / 2) + k0 / 2 + cu];
    }
    __syncthreads();
    if (k0 > qrow_max) continue;

    float sacc[8][4];
    #pragma unroll
    for (int nt = 0; nt < 8; nt++)
      #pragma unroll
      for (int c = 0; c < 4; c++) sacc[nt][c] = 0.f;

    #pragma unroll
    for (int ks = 0; ks < 16; ks++) {
      const int kk = ks * 8;
      const unsigned* qr0 = Qs + (m0 + g) * FL_QPITCH + kk + tk;
      const unsigned* qr1 = Qs + (m0 + 8 + g) * FL_QPITCH + kk + tk;
      unsigned a0 = qr0[0], a1 = qr1[0], a2 = qr0[4], a3 = qr1[4];
      #pragma unroll
      for (int nt = 0; nt < 8; nt++) {
        const unsigned* kr = Ks + (nt * 8 + g) * FL_QPITCH + kk + tk;
        mma_tf32(sacc[nt], a0, a1, a2, a3, kr[0], kr[4]);
      }
    }

    if (k0 + 63 > qb + m0) {
      const int r0q = qb + m0 + g, r1q = r0q + 8;
      #pragma unroll
      for (int nt = 0; nt < 8; nt++) {
        const int key0 = k0 + nt * 8 + 2 * tk;
        if (key0     > r0q) sacc[nt][0] = -1e30f;
        if (key0 + 1 > r0q) sacc[nt][1] = -1e30f;
        if (key0     > r1q) sacc[nt][2] = -1e30f;
        if (key0 + 1 > r1q) sacc[nt][3] = -1e30f;
      }
    }

    float mx0 = mrow0, mx1 = mrow1;
    #pragma unroll
    for (int nt = 0; nt < 8; nt++) {
      mx0 = fmaxf(mx0, fmaxf(sacc[nt][0], sacc[nt][1]));
      mx1 = fmaxf(mx1, fmaxf(sacc[nt][2], sacc[nt][3]));
    }
    mx0 = fmaxf(mx0, __shfl_xor_sync(0xffffffffu, mx0, 1));
    mx0 = fmaxf(mx0, __shfl_xor_sync(0xffffffffu, mx0, 2));
    mx1 = fmaxf(mx1, __shfl_xor_sync(0xffffffffu, mx1, 1));
    mx1 = fmaxf(mx1, __shfl_xor_sync(0xffffffffu, mx1, 2));
    const float al0 = __expf(mrow0 - mx0);
    const float al1 = __expf(mrow1 - mx1);
    mrow0 = mx0; mrow1 = mx1;
    lrow0 *= al0; lrow1 *= al1;

    const float af00 = __shfl_sync(0xffffffffu, al0, 8 * tk);
    const float af01 = __shfl_sync(0xffffffffu, al0, 8 * tk + 4);
    const float af10 = __shfl_sync(0xffffffffu, al1, 8 * tk);
    const float af11 = __shfl_sync(0xffffffffu, al1, 8 * tk + 4);
    #pragma unroll
    for (int mi = 0; mi < 8; mi++) {
      oacc[mi][0][0] *= af00; oacc[mi][0][1] *= af01;
      oacc[mi][0][2] *= af00; oacc[mi][0][3] *= af01;
      oacc[mi][1][0] *= af10; oacc[mi][1][1] *= af11;
      oacc[mi][1][2] *= af10; oacc[mi][1][3] *= af11;
    }

    float cb0 = 0.f, cb1 = 0.f;
    #pragma unroll
    for (int nt = 0; nt < 8; nt++) {
      sacc[nt][0] = __expf(sacc[nt][0] - mx0);
      sacc[nt][1] = __expf(sacc[nt][1] - mx0);
      sacc[nt][2] = __expf(sacc[nt][2] - mx1);
      sacc[nt][3] = __expf(sacc[nt][3] - mx1);
      cb0 += sacc[nt][0] + sacc[nt][1];
      cb1 += sacc[nt][2] + sacc[nt][3];
    }
    cb0 += __shfl_xor_sync(0xffffffffu, cb0, 1);
    cb0 += __shfl_xor_sync(0xffffffffu, cb0, 2);
    cb1 += __shfl_xor_sync(0xffffffffu, cb1, 1);
    cb1 += __shfl_xor_sync(0xffffffffu, cb1, 2);
    lrow0 += cb0; lrow1 += cb1;

    #pragma unroll
    for (int ks = 0; ks < 4; ks++) {
      const unsigned bl0 = packh2(sacc[2 * ks][0],     sacc[2 * ks][1]);
      const unsigned bl1 = packh2(sacc[2 * ks + 1][0], sacc[2 * ks + 1][1]);
      const unsigned bh0 = packh2(sacc[2 * ks][2],     sacc[2 * ks][3]);
      const unsigned bh1 = packh2(sacc[2 * ks + 1][2], sacc[2 * ks + 1][3]);
      #pragma unroll
      for (int mi = 0; mi < 8; mi++) {
        const unsigned* vr0 = Vt + (mi * 16 + g) * FL_VPITCH + ks * 8 + tk;
        const unsigned* vr1 = vr0 + 8 * FL_VPITCH;
        const unsigned va0 = vr0[0], va1 = vr1[0], va2 = vr0[4], va3 = vr1[4];
        mma_f16(oacc[mi][0], va0, va1, va2, va3, bl0, bl1);
        mma_f16(oacc[mi][1], va0, va1, va2, va3, bh0, bh1);
      }
    }
  }

  const float l00 = __shfl_sync(0xffffffffu, lrow0, 8 * tk);
  const float l01 = __shfl_sync(0xffffffffu, lrow0, 8 * tk + 4);
  const float l10 = __shfl_sync(0xffffffffu, lrow1, 8 * tk);
  const float l11 = __shfl_sync(0xffffffffu, lrow1, 8 * tk + 4);
  const float i00 = 1.f / l00, i01 = 1.f / l01;
  const float i10 = 1.f / l10, i11 = 1.f / l11;

  // ctx stores pre-rounded to tf32 so the output GEMM needs no conversion.
  float* cp = ctx + ((size_t)(b * NS + qb + m0)) * ND + h * NDH;
  #pragma unroll
  for (int mi = 0; mi < 8; mi++) {
    const int d0 = mi * 16 + g;
    cp[(size_t)(2 * tk) * ND + d0]         = __uint_as_float(f2tf(oacc[mi][0][0] * i00));
    cp[(size_t)(2 * tk + 1) * ND + d0]     = __uint_as_float(f2tf(oacc[mi][0][1] * i01));
    cp[(size_t)(2 * tk) * ND + d0 + 8]     = __uint_as_float(f2tf(oacc[mi][0][2] * i00));
    cp[(size_t)(2 * tk + 1) * ND + d0 + 8] = __uint_as_float(f2tf(oacc[mi][0][3] * i01));
    cp[(size_t)(8 + 2 * tk) * ND + d0]     = __uint_as_float(f2tf(oacc[mi][1][0] * i10));
    cp[(size_t)(9 + 2 * tk) * ND + d0]     = __uint_as_float(f2tf(oacc[mi][1][1] * i11));
    cp[(size_t)(8 + 2 * tk) * ND + d0 + 8] = __uint_as_float(f2tf(oacc[mi][1][2] * i10));
    cp[(size_t)(9 + 2 * tk) * ND + d0 + 8] = __uint_as_float(f2tf(oacc[mi][1][3] * i11));
  }
}

extern "C" void kernel_launch(void* const* d_in, const int* in_sizes, int n_in,
                              void* d_out, int out_size) {
  const float* x  = (const float*)d_in[0];
  const float* fc = (const float*)d_in[1];
  const float* fs = (const float*)d_in[2];
  // d_in[3] is the mask; causal handled analytically
  const float* wq = (const float*)d_in[4];
  const float* wk = (const float*)d_in[5];
  const float* wv = (const float*)d_in[6];
  const float* wo = (const float*)d_in[7];

  float *q, *k, *ctx, *xt, *wqt, *wkt, *wvt, *wot;
  __half* vt;
  cudaGetSymbolAddress((void**)&q,   g_q);
  cudaGetSymbolAddress((void**)&k,   g_k);
  cudaGetSymbolAddress((void**)&vt,  g_vt);
  cudaGetSymbolAddress((void**)&ctx, g_ctx);
  cudaGetSymbolAddress((void**)&xt,  g_xt);
  cudaGetSymbolAddress((void**)&wqt, g_wqt);
  cudaGetSymbolAddress((void**)&wkt, g_wkt);
  cudaGetSymbolAddress((void**)&wvt, g_wvt);
  cudaGetSymbolAddress((void**)&wot, g_wot);

  cudaFuncSetAttribute(flash_tc, cudaFuncAttributeMaxDynamicSharedMemorySize, FL_SMEM);
  cudaFuncSetAttribute(gemm_tc<0>, cudaFuncAttributeMaxDynamicSharedMemorySize, GM_SMEM);
  cudaFuncSetAttribute(gemm_tc<2>, cudaFuncAttributeMaxDynamicSharedMemorySize, GM_SMEM);
  cudaFuncSetAttribute(gemm_tc<3>, cudaFuncAttributeMaxDynamicSharedMemorySize, GM_SMEM);

  // Prep: tf32-round x and weights once.
  const int nx4 = NM * ND / 4, nw4 = ND * ND / 4;
  round_tf32_k<<<nx4 / 256, 256>>>(x, xt, nx4);
  round_tf32_k<<<nw4 / 256, 256>>>(wq, wqt, nw4);
  round_tf32_k<<<nw4 / 256, 256>>>(wk, wkt, nw4);
  round_tf32_k<<<nw4 / 256, 256>>>(wv, wvt, nw4);
  round_tf32_k<<<nw4 / 256, 256>>>(wo, wot, nw4);

  dim3 gg(ND / 128, NM / 128);
  gemm_tc<2><<<gg, 256, GM_SMEM>>>(xt, wqt, q, nullptr, fc, fs);
  gemm_tc<2><<<gg, 256, GM_SMEM>>>(xt, wkt, k, nullptr, fc, fs);
  gemm_tc<3><<<gg, 256, GM_SMEM>>>(xt, wvt, nullptr, vt, nullptr, nullptr);

  dim3 fg(NS / 128, NB * NH);
  flash_tc<<<fg, 256, FL_SMEM>>>(q, k, vt, ctx);

  gemm_tc<0><<<gg, 256, GM_SMEM>>>(ctx, wot, (float*)d_out, nullptr, nullptr, nullptr);
}

// round 8
// speedup vs baseline: 10.8284x; 1.3673x over previous
#include <cuda_runtime.h>
#include <cuda_fp16.h>
#include <stdint.h>
#include <math.h>

#define NB 2
#define NS 2048
#define ND 2048
#define NH 16
#define NDH 128
#define NM (NB*NS)

// Scratch (device globals; no allocation allowed)
__device__ __half g_qh[(size_t)NB*NH*NS*NDH];
__device__ __half g_kh[(size_t)NB*NH*NS*NDH];
__device__ __half g_vt[(size_t)NB*NH*NDH*NS];   // V transposed: [b,h,dh,s] fp16
__device__ __half g_ctx[(size_t)NB*NS*ND];      // attention output, fp16
__device__ __half g_xh[(size_t)NM*ND];          // x in fp16
__device__ __half g_wqh[(size_t)ND*ND];
__device__ __half g_wkh[(size_t)ND*ND];
__device__ __half g_wvh[(size_t)ND*ND];
__device__ __half g_woh[(size_t)ND*ND];

__device__ __forceinline__ unsigned packh2(float lo, float hi) {
  __half2 h = __floats2half2_rn(lo, hi);
  return *(unsigned*)&h;
}
__device__ __forceinline__ void mma_f16(float* c, unsigned a0, unsigned a1,
                                        unsigned a2, unsigned a3,
                                        unsigned b0, unsigned b1) {
  asm volatile(
    "mma.sync.aligned.m16n8k16.row.col.f32.f16.f16.f32 "
    "{%0,%1,%2,%3},{%4,%5,%6,%7},{%8,%9},{%0,%1,%2,%3};\n"
    : "+f"(c[0]), "+f"(c[1]), "+f"(c[2]), "+f"(c[3])
    : "r"(a0), "r"(a1), "r"(a2), "r"(a3), "r"(b0), "r"(b1));
}
__device__ __forceinline__ void cpasync16(uint32_t dst, const void* src) {
  asm volatile("cp.async.cg.shared.global [%0], [%1], 16;" :: "r"(dst),
               "l"(src));
}

// fp32 -> fp16 conversion, vectorized.
__global__ void tohalf_k(const float* __restrict__ src,
                         __half* __restrict__ dst, int n4) {
  int i = blockIdx.x * 256 + threadIdx.x;
  if (i < n4) {
    float4 v = ((const float4*)src)[i];
    __half2 h0 = __floats2half2_rn(v.x, v.y);
    __half2 h1 = __floats2half2_rn(v.z, v.w);
    uint2 u = {*(unsigned*)&h0, *(unsigned*)&h1};
    ((uint2*)dst)[i] = u;
  }
}

// ============================================================================
// GEMM: C[M,N] = A[M,K] * W[N,K]^T, fp16 mma.sync (m16n8k16, fp32 accum),
// cp.async 3-stage pipeline. Block 128x128, K-tile 32, 256 thr = 8 warps
// (2x4), warp tile 64x32. Smem rows: 32 halves = 16 words, padded to pitch 20
// words (bank-conflict-free fragment loads: (20g+tk) mod 32 all distinct).
// MODE 0: fp32 row-major store; MODE 2: fp16 head scatter + RoPE (+outscale);
// MODE 3: fp16 transposed scatter [b,h,dh,s].
// ============================================================================
#define GH_STAGEW 2560                 // 128 rows * 20 words
#define GH_SMEM (3 * 2 * GH_STAGEW * 4)

template<int MODE>
__global__ void __launch_bounds__(256, 2) gemm_h(
    const __half* __restrict__ A, const __half* __restrict__ W,
    float* __restrict__ C, __half* __restrict__ Ch,
    const float* __restrict__ fcos, const float* __restrict__ fsin,
    float outscale)
{
  extern __shared__ unsigned smh[];
  unsigned* As = smh;                    // [3][128][20]
  unsigned* Bs = smh + 3 * GH_STAGEW;
  const int K = ND;
  const int bm = blockIdx.y * 128;
  const int bn = blockIdx.x * 128;
  const int tid = threadIdx.x;
  const int warp = tid >> 5, lane = tid & 31;
  const int wm0 = (warp >> 2) * 64;
  const int wn0 = (warp & 3) * 32;
  const int g = lane >> 2, tk = lane & 3;

  const uint32_t sa = (uint32_t)__cvta_generic_to_shared(As);
  const uint32_t sbm = (uint32_t)__cvta_generic_to_shared(Bs);

  float acc[4][4][4];
  #pragma unroll
  for (int mi = 0; mi < 4; mi++)
    #pragma unroll
    for (int ni = 0; ni < 4; ni++)
      #pragma unroll
      for (int cc = 0; cc < 4; cc++) acc[mi][ni][cc] = 0.f;

  // copy: 512 16B-chunks per matrix per tile; thread -> 2 chunks each.
  #define GH_ISSUE(kt, st) do { \
    _Pragma("unroll") \
    for (int i = 0; i < 2; i++) { \
      const int id = tid + 256 * i; \
      const int r = id >> 2, c = id & 3; \
      const uint32_t wo = (uint32_t)((st) * GH_STAGEW + r * 20 + c * 4) * 4; \
      cpasync16(sa + wo, A + (size_t)(bm + r) * K + (kt) * 32 + c * 8); \
      cpasync16(sbm + wo, W + (size_t)(bn + r) * K + (kt) * 32 + c * 8); \
    } \
    asm volatile("cp.async.commit_group;" ::); \
  } while (0)

  GH_ISSUE(0, 0);
  GH_ISSUE(1, 1);

  const int niter = K / 32;   // 64
  int st_c = 0, st_p = 2;
  for (int kt = 0; kt < niter; kt++) {
    asm volatile("cp.async.wait_group 1;" ::);
    __syncthreads();
    if (kt + 2 < niter) GH_ISSUE(kt + 2, st_p);
    else asm volatile("cp.async.commit_group;" ::);

    const unsigned* a = As + st_c * GH_STAGEW;
    const unsigned* b = Bs + st_c * GH_STAGEW;
    #pragma unroll
    for (int ks = 0; ks < 2; ks++) {
      const int wb = 8 * ks + tk;
      unsigned afr[4][4], bfr[4][2];
      #pragma unroll
      for (int mi = 0; mi < 4; mi++) {
        const int m = wm0 + mi * 16 + g;
        afr[mi][0] = a[m * 20 + wb];
        afr[mi][1] = a[(m + 8) * 20 + wb];
        afr[mi][2] = a[m * 20 + wb + 4];
        afr[mi][3] = a[(m + 8) * 20 + wb + 4];
      }
      #pragma unroll
      for (int ni = 0; ni < 4; ni++) {
        const int n = wn0 + ni * 8 + g;
        bfr[ni][0] = b[n * 20 + wb];
        bfr[ni][1] = b[n * 20 + wb + 4];
      }
      #pragma unroll
      for (int mi = 0; mi < 4; mi++)
        #pragma unroll
        for (int ni = 0; ni < 4; ni++)
          mma_f16(acc[mi][ni], afr[mi][0], afr[mi][1], afr[mi][2], afr[mi][3],
                  bfr[ni][0], bfr[ni][1]);
    }
    st_c = (st_c == 2) ? 0 : st_c + 1;
    st_p = (st_p == 2) ? 0 : st_p + 1;
    __syncthreads();
  }

  #pragma unroll
  for (int mi = 0; mi < 4; mi++) {
    #pragma unroll
    for (int half = 0; half < 2; half++) {
      const int m = bm + wm0 + mi * 16 + g + half * 8;
      const int b = m / NS, s = m % NS;
      #pragma unroll
      for (int ni = 0; ni < 4; ni++) {
        float v0 = acc[mi][ni][half * 2 + 0];
        float v1 = acc[mi][ni][half * 2 + 1];
        const int n = bn + wn0 + ni * 8 + tk * 2;
        if (MODE == 0) {
          float2 vv = {v0, v1};
          *(float2*)&C[(size_t)m * ND + n] = vv;
        } else if (MODE == 3) {
          const int h = n / NDH, d = n % NDH;
          __half* dst = Ch + (((size_t)(b * NH + h)) * NDH + d) * NS + s;
          dst[0]  = __float2half_rn(v0);
          dst[NS] = __float2half_rn(v1);
        } else {  // MODE 2
          const int h = n / NDH, d = n % NDH;
          __half* dst = Ch + (((size_t)(b * NH + h)) * NS + s) * NDH;
          const int pi = d >> 1;
          const float cc = fcos[s * (NDH / 2) + pi];
          const float sn = fsin[s * (NDH / 2) + pi];
          v0 *= outscale; v1 *= outscale;
          __half2 vv = __floats2half2_rn(v0 * cc - v1 * sn, v0 * sn + v1 * cc);
          *(__half2*)&dst[d] = vv;
        }
      }
    }
  }
}

// ============================================================================
// Flash attention (causal), all-fp16 mma. Br=128 (8 warps x 16 rows), Bc=64.
// S = Q*K^T fp16 (scale pre-folded into Q); O^T = V^T * P^T fp16.
// Smem (words): Qs[128][68], Ks[64][68], Vt[128][36]. Pitch 68 -> banks
// (68g+tk) mod 32 = 4g+tk, conflict-free.
// ============================================================================
#define FL_QPITCH 68
#define FL_VPITCH 36
#define FL_SMEM ((128*FL_QPITCH + 64*FL_QPITCH + 128*FL_VPITCH) * 4)

__global__ void __launch_bounds__(256) flash_tc(
    const __half* __restrict__ gq, const __half* __restrict__ gk,
    const __half* __restrict__ gvt, __half* __restrict__ ctx)
{
  extern __shared__ unsigned smf[];
  unsigned* Qs = smf;
  unsigned* Ks = smf + 128 * FL_QPITCH;
  unsigned* Vt = smf + 128 * FL_QPITCH + 64 * FL_QPITCH;

  const int bh = blockIdx.y;
  const int b = bh >> 4, h = bh & 15;
  const int qb = blockIdx.x * 128;
  const int tid = threadIdx.x;
  const int warp = tid >> 5, lane = tid & 31;
  const int g = lane >> 2, tk = lane & 3;
  const int m0 = warp * 16;
  const int qrow_max = qb + m0 + 15;

  // Load Q tile (raw fp16 copy; scale already folded in by the Q-GEMM)
  const __half* qbase = gq + ((size_t)bh * NS + qb) * NDH;
  #pragma unroll
  for (int i = 0; i < 8; i++) {
    int idx = i * 256 + tid;
    int row = idx >> 4, c = idx & 15;
    uint4 v = *(const uint4*)(qbase + (size_t)row * NDH + c * 8);
    *(uint4*)(Qs + row * FL_QPITCH + c * 4) = v;
  }

  float oacc[8][2][4];
  #pragma unroll
  for (int mi = 0; mi < 8; mi++)
    #pragma unroll
    for (int nt = 0; nt < 2; nt++)
      #pragma unroll
      for (int c = 0; c < 4; c++) oacc[mi][nt][c] = 0.f;
  float mrow0 = -1e30f, mrow1 = -1e30f, lrow0 = 0.f, lrow1 = 0.f;

  const __half* kbase = gk + (size_t)bh * NS * NDH;
  const unsigned* vtbase = (const unsigned*)(gvt + (size_t)bh * NDH * NS);
  const int ntiles = qb / 64 + 2;
  __syncthreads();

  for (int t = 0; t < ntiles; t++) {
    const int k0 = t * 64;
    __syncthreads();
    // K tile: 64x128 fp16
    #pragma unroll
    for (int i = 0; i < 4; i++) {
      int idx = i * 256 + tid;
      int row = idx >> 4, c = idx & 15;
      uint4 v = *(const uint4*)(kbase + (size_t)(k0 + row) * NDH + c * 8);
      *(uint4*)(Ks + row * FL_QPITCH + c * 4) = v;
    }
    // Vt tile: 128 rows x 32 words (64 halves)
    #pragma unroll
    for (int i = 0; i < 16; i++) {
      int idx = i * 256 + tid;
      int row = idx >> 5, cu = idx & 31;
      Vt[row * FL_VPITCH + cu] = vtbase[(size_t)row * (NS / 2) + k0 / 2 + cu];
    }
    __syncthreads();
    if (k0 > qrow_max) continue;

    // ---- S = Q K^T (fp16, fp32 accum) ----
    float sacc[8][4];
    #pragma unroll
    for (int nt = 0; nt < 8; nt++)
      #pragma unroll
      for (int c = 0; c < 4; c++) sacc[nt][c] = 0.f;

    #pragma unroll
    for (int ks = 0; ks < 8; ks++) {
      const int wb = 8 * ks + tk;
      const unsigned* qr0 = Qs + (m0 + g) * FL_QPITCH + wb;
      const unsigned* qr1 = Qs + (m0 + 8 + g) * FL_QPITCH + wb;
      const unsigned a0 = qr0[0], a1 = qr1[0], a2 = qr0[4], a3 = qr1[4];
      #pragma unroll
      for (int nt = 0; nt < 8; nt++) {
        const unsigned* kr = Ks + (nt * 8 + g) * FL_QPITCH + wb;
        mma_f16(sacc[nt], a0, a1, a2, a3, kr[0], kr[4]);
      }
    }

    // ---- causal mask (near diagonal only) ----
    if (k0 + 63 > qb + m0) {
      const int r0q = qb + m0 + g, r1q = r0q + 8;
      #pragma unroll
      for (int nt = 0; nt < 8; nt++) {
        const int key0 = k0 + nt * 8 + 2 * tk;
        if (key0     > r0q) sacc[nt][0] = -1e30f;
        if (key0 + 1 > r0q) sacc[nt][1] = -1e30f;
        if (key0     > r1q) sacc[nt][2] = -1e30f;
        if (key0 + 1 > r1q) sacc[nt][3] = -1e30f;
      }
    }

    // ---- online softmax ----
    float mx0 = mrow0, mx1 = mrow1;
    #pragma unroll
    for (int nt = 0; nt < 8; nt++) {
      mx0 = fmaxf(mx0, fmaxf(sacc[nt][0], sacc[nt][1]));
      mx1 = fmaxf(mx1, fmaxf(sacc[nt][2], sacc[nt][3]));
    }
    mx0 = fmaxf(mx0, __shfl_xor_sync(0xffffffffu, mx0, 1));
    mx0 = fmaxf(mx0, __shfl_xor_sync(0xffffffffu, mx0, 2));
    mx1 = fmaxf(mx1, __shfl_xor_sync(0xffffffffu, mx1, 1));
    mx1 = fmaxf(mx1, __shfl_xor_sync(0xffffffffu, mx1, 2));
    const float al0 = __expf(mrow0 - mx0);
    const float al1 = __expf(mrow1 - mx1);
    mrow0 = mx0; mrow1 = mx1;
    lrow0 *= al0; lrow1 *= al1;

    const float af00 = __shfl_sync(0xffffffffu, al0, 8 * tk);
    const float af01 = __shfl_sync(0xffffffffu, al0, 8 * tk + 4);
    const float af10 = __shfl_sync(0xffffffffu, al1, 8 * tk);
    const float af11 = __shfl_sync(0xffffffffu, al1, 8 * tk + 4);
    #pragma unroll
    for (int mi = 0; mi < 8; mi++) {
      oacc[mi][0][0] *= af00; oacc[mi][0][1] *= af01;
      oacc[mi][0][2] *= af00; oacc[mi][0][3] *= af01;
      oacc[mi][1][0] *= af10; oacc[mi][1][1] *= af11;
      oacc[mi][1][2] *= af10; oacc[mi][1][3] *= af11;
    }

    float cb0 = 0.f, cb1 = 0.f;
    #pragma unroll
    for (int nt = 0; nt < 8; nt++) {
      sacc[nt][0] = __expf(sacc[nt][0] - mx0);
      sacc[nt][1] = __expf(sacc[nt][1] - mx0);
      sacc[nt][2] = __expf(sacc[nt][2] - mx1);
      sacc[nt][3] = __expf(sacc[nt][3] - mx1);
      cb0 += sacc[nt][0] + sacc[nt][1];
      cb1 += sacc[nt][2] + sacc[nt][3];
    }
    cb0 += __shfl_xor_sync(0xffffffffu, cb0, 1);
    cb0 += __shfl_xor_sync(0xffffffffu, cb0, 2);
    cb1 += __shfl_xor_sync(0xffffffffu, cb1, 1);
    cb1 += __shfl_xor_sync(0xffffffffu, cb1, 2);
    lrow0 += cb0; lrow1 += cb1;

    // ---- O^T += V^T * P^T (fp16); P^T fragments direct from sacc ----
    #pragma unroll
    for (int ks = 0; ks < 4; ks++) {
      const unsigned bl0 = packh2(sacc[2 * ks][0],     sacc[2 * ks][1]);
      const unsigned bl1 = packh2(sacc[2 * ks + 1][0], sacc[2 * ks + 1][1]);
      const unsigned bh0 = packh2(sacc[2 * ks][2],     sacc[2 * ks][3]);
      const unsigned bh1 = packh2(sacc[2 * ks + 1][2], sacc[2 * ks + 1][3]);
      #pragma unroll
      for (int mi = 0; mi < 8; mi++) {
        const unsigned* vr0 = Vt + (mi * 16 + g) * FL_VPITCH + ks * 8 + tk;
        const unsigned* vr1 = vr0 + 8 * FL_VPITCH;
        const unsigned va0 = vr0[0], va1 = vr1[0], va2 = vr0[4], va3 = vr1[4];
        mma_f16(oacc[mi][0], va0, va1, va2, va3, bl0, bl1);
        mma_f16(oacc[mi][1], va0, va1, va2, va3, bh0, bh1);
      }
    }
  }

  // ---- normalize + store ctx (fp16; O^T layout: m=dh, n=qrow) ----
  const float l00 = __shfl_sync(0xffffffffu, lrow0, 8 * tk);
  const float l01 = __shfl_sync(0xffffffffu, lrow0, 8 * tk + 4);
  const float l10 = __shfl_sync(0xffffffffu, lrow1, 8 * tk);
  const float l11 = __shfl_sync(0xffffffffu, lrow1, 8 * tk + 4);
  const float i00 = 1.f / l00, i01 = 1.f / l01;
  const float i10 = 1.f / l10, i11 = 1.f / l11;

  __half* cp = ctx + ((size_t)(b * NS + qb + m0)) * ND + h * NDH;
  #pragma unroll
  for (int mi = 0; mi < 8; mi++) {
    const int d0 = mi * 16 + g;
    cp[(size_t)(2 * tk) * ND + d0]         = __float2half_rn(oacc[mi][0][0] * i00);
    cp[(size_t)(2 * tk + 1) * ND + d0]     = __float2half_rn(oacc[mi][0][1] * i01);
    cp[(size_t)(2 * tk) * ND + d0 + 8]     = __float2half_rn(oacc[mi][0][2] * i00);
    cp[(size_t)(2 * tk + 1) * ND + d0 + 8] = __float2half_rn(oacc[mi][0][3] * i01);
    cp[(size_t)(8 + 2 * tk) * ND + d0]     = __float2half_rn(oacc[mi][1][0] * i10);
    cp[(size_t)(9 + 2 * tk) * ND + d0]     = __float2half_rn(oacc[mi][1][1] * i11);
    cp[(size_t)(8 + 2 * tk) * ND + d0 + 8] = __float2half_rn(oacc[mi][1][2] * i10);
    cp[(size_t)(9 + 2 * tk) * ND + d0 + 8] = __float2half_rn(oacc[mi][1][3] * i11);
  }
}

extern "C" void kernel_launch(void* const* d_in, const int* in_sizes, int n_in,
                              void* d_out, int out_size) {
  const float* x  = (const float*)d_in[0];
  const float* fc = (const float*)d_in[1];
  const float* fs = (const float*)d_in[2];
  // d_in[3] is the mask; causal handled analytically
  const float* wq = (const float*)d_in[4];
  const float* wk = (const float*)d_in[5];
  const float* wv = (const float*)d_in[6];
  const float* wo = (const float*)d_in[7];

  __half *qh, *kh, *vt, *ctx, *xh, *wqh, *wkh, *wvh, *woh;
  cudaGetSymbolAddress((void**)&qh,  g_qh);
  cudaGetSymbolAddress((void**)&kh,  g_kh);
  cudaGetSymbolAddress((void**)&vt,  g_vt);
  cudaGetSymbolAddress((void**)&ctx, g_ctx);
  cudaGetSymbolAddress((void**)&xh,  g_xh);
  cudaGetSymbolAddress((void**)&wqh, g_wqh);
  cudaGetSymbolAddress((void**)&wkh, g_wkh);
  cudaGetSymbolAddress((void**)&wvh, g_wvh);
  cudaGetSymbolAddress((void**)&woh, g_woh);

  cudaFuncSetAttribute(flash_tc, cudaFuncAttributeMaxDynamicSharedMemorySize, FL_SMEM);
  cudaFuncSetAttribute(gemm_h<0>, cudaFuncAttributeMaxDynamicSharedMemorySize, GH_SMEM);
  cudaFuncSetAttribute(gemm_h<2>, cudaFuncAttributeMaxDynamicSharedMemorySize, GH_SMEM);
  cudaFuncSetAttribute(gemm_h<3>, cudaFuncAttributeMaxDynamicSharedMemorySize, GH_SMEM);

  // Prep: convert x and weights to fp16 once.
  const int nx4 = NM * ND / 4, nw4 = ND * ND / 4;
  tohalf_k<<<nx4 / 256, 256>>>(x, xh, nx4);
  tohalf_k<<<nw4 / 256, 256>>>(wq, wqh, nw4);
  tohalf_k<<<nw4 / 256, 256>>>(wk, wkh, nw4);
  tohalf_k<<<nw4 / 256, 256>>>(wv, wvh, nw4);
  tohalf_k<<<nw4 / 256, 256>>>(wo, woh, nw4);

  const float scale = 0.08838834764831845f;  // 1/sqrt(128)
  dim3 gg(ND / 128, NM / 128);
  gemm_h<2><<<gg, 256, GH_SMEM>>>(xh, wqh, nullptr, qh, fc, fs, scale);
  gemm_h<2><<<gg, 256, GH_SMEM>>>(xh, wkh, nullptr, kh, fc, fs, 1.0f);
  gemm_h<3><<<gg, 256, GH_SMEM>>>(xh, wvh, nullptr, vt, nullptr, nullptr, 1.0f);

  dim3 fg(NS / 128, NB * NH);
  flash_tc<<<fg, 256, FL_SMEM>>>(qh, kh, vt, ctx);

  gemm_h<0><<<gg, 256, GH_SMEM>>>(ctx, woh, (float*)d_out, nullptr, nullptr, nullptr, 1.0f);
}

// round 9
// speedup vs baseline: 11.2609x; 1.0399x over previous
#include <cuda_runtime.h>
#include <cuda_fp16.h>
#include <stdint.h>
#include <math.h>

#define NB 2
#define NS 2048
#define ND 2048
#define NH 16
#define NDH 128
#define NM (NB*NS)

// Scratch (device globals; no allocation allowed)
__device__ __half g_qh[(size_t)NB*NH*NS*NDH];
__device__ __half g_kh[(size_t)NB*NH*NS*NDH];
__device__ __half g_vt[(size_t)NB*NH*NDH*NS];   // V transposed: [b,h,dh,s] fp16
__device__ __half g_ctx[(size_t)NB*NS*ND];      // attention output, fp16
__device__ __half g_xh[(size_t)NM*ND];          // x in fp16
__device__ __half g_wqh[(size_t)ND*ND];
__device__ __half g_wkh[(size_t)ND*ND];
__device__ __half g_wvh[(size_t)ND*ND];
__device__ __half g_woh[(size_t)ND*ND];

__device__ __forceinline__ unsigned packh2(float lo, float hi) {
  __half2 h = __floats2half2_rn(lo, hi);
  return *(unsigned*)&h;
}
__device__ __forceinline__ void mma_f16(float* c, unsigned a0, unsigned a1,
                                        unsigned a2, unsigned a3,
                                        unsigned b0, unsigned b1) {
  asm volatile(
    "mma.sync.aligned.m16n8k16.row.col.f32.f16.f16.f32 "
    "{%0,%1,%2,%3},{%4,%5,%6,%7},{%8,%9},{%0,%1,%2,%3};\n"
    : "+f"(c[0]), "+f"(c[1]), "+f"(c[2]), "+f"(c[3])
    : "r"(a0), "r"(a1), "r"(a2), "r"(a3), "r"(b0), "r"(b1));
}
__device__ __forceinline__ void cpasync16(uint32_t dst, const void* src) {
  asm volatile("cp.async.cg.shared.global [%0], [%1], 16;" :: "r"(dst),
               "l"(src));
}

// fp32 -> fp16 conversion, vectorized.
__global__ void tohalf_k(const float* __restrict__ src,
                         __half* __restrict__ dst, int n4) {
  int i = blockIdx.x * 256 + threadIdx.x;
  if (i < n4) {
    float4 v = ((const float4*)src)[i];
    __half2 h0 = __floats2half2_rn(v.x, v.y);
    __half2 h1 = __floats2half2_rn(v.z, v.w);
    uint2 u = {*(unsigned*)&h0, *(unsigned*)&h1};
    ((uint2*)dst)[i] = u;
  }
}

// 4 weight matrices (ND*ND each) in one launch.
__global__ void tohalf4_k(const float* __restrict__ s0, const float* __restrict__ s1,
                          const float* __restrict__ s2, const float* __restrict__ s3,
                          __half* __restrict__ d0, __half* __restrict__ d1,
                          __half* __restrict__ d2, __half* __restrict__ d3) {
  const int per = (ND * ND / 4) / 256;       // blocks per tensor
  const int which = blockIdx.x / per;
  const int i = (blockIdx.x % per) * 256 + threadIdx.x;
  const float* src = (which == 0) ? s0 : (which == 1) ? s1 : (which == 2) ? s2 : s3;
  __half* dst = (which == 0) ? d0 : (which == 1) ? d1 : (which == 2) ? d2 : d3;
  float4 v = ((const float4*)src)[i];
  __half2 h0 = __floats2half2_rn(v.x, v.y);
  __half2 h1 = __floats2half2_rn(v.z, v.w);
  uint2 u = {*(unsigned*)&h0, *(unsigned*)&h1};
  ((uint2*)dst)[i] = u;
}

// ============================================================================
// GEMM (unchanged from R8): fp16 mma.sync, cp.async 3-stage, 128x128 tile.
// ============================================================================
#define GH_STAGEW 2560                 // 128 rows * 20 words
#define GH_SMEM (3 * 2 * GH_STAGEW * 4)

template<int MODE>
__global__ void __launch_bounds__(256, 2) gemm_h(
    const __half* __restrict__ A, const __half* __restrict__ W,
    float* __restrict__ C, __half* __restrict__ Ch,
    const float* __restrict__ fcos, const float* __restrict__ fsin,
    float outscale)
{
  extern __shared__ unsigned smh[];
  unsigned* As = smh;                    // [3][128][20]
  unsigned* Bs = smh + 3 * GH_STAGEW;
  const int K = ND;
  const int bm = blockIdx.y * 128;
  const int bn = blockIdx.x * 128;
  const int tid = threadIdx.x;
  const int warp = tid >> 5, lane = tid & 31;
  const int wm0 = (warp >> 2) * 64;
  const int wn0 = (warp & 3) * 32;
  const int g = lane >> 2, tk = lane & 3;

  const uint32_t sa = (uint32_t)__cvta_generic_to_shared(As);
  const uint32_t sbm = (uint32_t)__cvta_generic_to_shared(Bs);

  float acc[4][4][4];
  #pragma unroll
  for (int mi = 0; mi < 4; mi++)
    #pragma unroll
    for (int ni = 0; ni < 4; ni++)
      #pragma unroll
      for (int cc = 0; cc < 4; cc++) acc[mi][ni][cc] = 0.f;

  #define GH_ISSUE(kt, st) do { \
    _Pragma("unroll") \
    for (int i = 0; i < 2; i++) { \
      const int id = tid + 256 * i; \
      const int r = id >> 2, c = id & 3; \
      const uint32_t wo = (uint32_t)((st) * GH_STAGEW + r * 20 + c * 4) * 4; \
      cpasync16(sa + wo, A + (size_t)(bm + r) * K + (kt) * 32 + c * 8); \
      cpasync16(sbm + wo, W + (size_t)(bn + r) * K + (kt) * 32 + c * 8); \
    } \
    asm volatile("cp.async.commit_group;" ::); \
  } while (0)

  GH_ISSUE(0, 0);
  GH_ISSUE(1, 1);

  const int niter = K / 32;   // 64
  int st_c = 0, st_p = 2;
  for (int kt = 0; kt < niter; kt++) {
    asm volatile("cp.async.wait_group 1;" ::);
    __syncthreads();
    if (kt + 2 < niter) GH_ISSUE(kt + 2, st_p);
    else asm volatile("cp.async.commit_group;" ::);

    const unsigned* a = As + st_c * GH_STAGEW;
    const unsigned* b = Bs + st_c * GH_STAGEW;
    #pragma unroll
    for (int ks = 0; ks < 2; ks++) {
      const int wb = 8 * ks + tk;
      unsigned afr[4][4], bfr[4][2];
      #pragma unroll
      for (int mi = 0; mi < 4; mi++) {
        const int m = wm0 + mi * 16 + g;
        afr[mi][0] = a[m * 20 + wb];
        afr[mi][1] = a[(m + 8) * 20 + wb];
        afr[mi][2] = a[m * 20 + wb + 4];
        afr[mi][3] = a[(m + 8) * 20 + wb + 4];
      }
      #pragma unroll
      for (int ni = 0; ni < 4; ni++) {
        const int n = wn0 + ni * 8 + g;
        bfr[ni][0] = b[n * 20 + wb];
        bfr[ni][1] = b[n * 20 + wb + 4];
      }
      #pragma unroll
      for (int mi = 0; mi < 4; mi++)
        #pragma unroll
        for (int ni = 0; ni < 4; ni++)
          mma_f16(acc[mi][ni], afr[mi][0], afr[mi][1], afr[mi][2], afr[mi][3],
                  bfr[ni][0], bfr[ni][1]);
    }
    st_c = (st_c == 2) ? 0 : st_c + 1;
    st_p = (st_p == 2) ? 0 : st_p + 1;
    __syncthreads();
  }

  #pragma unroll
  for (int mi = 0; mi < 4; mi++) {
    #pragma unroll
    for (int half = 0; half < 2; half++) {
      const int m = bm + wm0 + mi * 16 + g + half * 8;
      const int b = m / NS, s = m % NS;
      #pragma unroll
      for (int ni = 0; ni < 4; ni++) {
        float v0 = acc[mi][ni][half * 2 + 0];
        float v1 = acc[mi][ni][half * 2 + 1];
        const int n = bn + wn0 + ni * 8 + tk * 2;
        if (MODE == 0) {
          float2 vv = {v0, v1};
          *(float2*)&C[(size_t)m * ND + n] = vv;
        } else if (MODE == 3) {
          const int h = n / NDH, d = n % NDH;
          __half* dst = Ch + (((size_t)(b * NH + h)) * NDH + d) * NS + s;
          dst[0]  = __float2half_rn(v0);
          dst[NS] = __float2half_rn(v1);
        } else {  // MODE 2
          const int h = n / NDH, d = n % NDH;
          __half* dst = Ch + (((size_t)(b * NH + h)) * NS + s) * NDH;
          const int pi = d >> 1;
          const float cc = fcos[s * (NDH / 2) + pi];
          const float sn = fsin[s * (NDH / 2) + pi];
          v0 *= outscale; v1 *= outscale;
          __half2 vv = __floats2half2_rn(v0 * cc - v1 * sn, v0 * sn + v1 * cc);
          *(__half2*)&dst[d] = vv;
        }
      }
    }
  }
}

// ============================================================================
// Flash attention (causal), all-fp16 mma, cp.async 3-stage K/V pipeline.
// Br=128 (8 warps x 16 rows), Bc=64. Smem (words): Qs[128][68] +
// 3 stages of (Ks[64][68] + Vt[128][36]).
// ============================================================================
#define FL_QPITCH 68
#define FL_VPITCH 36
#define FL_KWORDS (64 * FL_QPITCH)                 // 4352
#define FL_VWORDS (128 * FL_VPITCH)                // 4608
#define FL_STAGEW (FL_KWORDS + FL_VWORDS)          // 8960
#define FL_SMEM ((128 * FL_QPITCH + 3 * FL_STAGEW) * 4)

__global__ void __launch_bounds__(256) flash_tc(
    const __half* __restrict__ gq, const __half* __restrict__ gk,
    const __half* __restrict__ gvt, __half* __restrict__ ctx)
{
  extern __shared__ unsigned smf[];
  unsigned* Qs = smf;
  unsigned* St = smf + 128 * FL_QPITCH;   // 3 stages

  const int bh = blockIdx.y;
  const int b = bh >> 4, h = bh & 15;
  const int qb = blockIdx.x * 128;
  const int tid = threadIdx.x;
  const int warp = tid >> 5, lane = tid & 31;
  const int g = lane >> 2, tk = lane & 3;
  const int m0 = warp * 16;
  const int qrow_max = qb + m0 + 15;

  const __half* kbase = gk + (size_t)bh * NS * NDH;
  const __half* vtb = gvt + (size_t)bh * NDH * NS;
  const int ntiles = qb / 64 + 2;
  const uint32_t sSt = (uint32_t)__cvta_generic_to_shared(St);

  // cp.async issue of K/V tile t into stage s (empty-commit past the end)
  #define FL_ISSUE(t, s) do { \
    if ((t) < ntiles) { \
      const int k0i = (t) * 64; \
      const uint32_t kd = sSt + (uint32_t)(s) * FL_STAGEW * 4; \
      const uint32_t vd = kd + FL_KWORDS * 4; \
      _Pragma("unroll") \
      for (int i = 0; i < 4; i++) { \
        const int id = tid + 256 * i; \
        const int kr = id >> 4, kc = id & 15; \
        cpasync16(kd + (uint32_t)(kr * FL_QPITCH + kc * 4) * 4, \
                  kbase + (size_t)(k0i + kr) * NDH + kc * 8); \
        const int vr = id >> 3, vc = id & 7; \
        cpasync16(vd + (uint32_t)(vr * FL_VPITCH + vc * 4) * 4, \
                  vtb + (size_t)vr * NS + k0i + vc * 8); \
      } \
    } \
    asm volatile("cp.async.commit_group;" ::); \
  } while (0)

  FL_ISSUE(0, 0);
  FL_ISSUE(1, 1);

  // Load Q tile (scale already folded in by the Q-GEMM)
  const __half* qbase = gq + ((size_t)bh * NS + qb) * NDH;
  #pragma unroll
  for (int i = 0; i < 8; i++) {
    int idx = i * 256 + tid;
    int row = idx >> 4, c = idx & 15;
    uint4 v = *(const uint4*)(qbase + (size_t)row * NDH + c * 8);
    *(uint4*)(Qs + row * FL_QPITCH + c * 4) = v;
  }

  float oacc[8][2][4];
  #pragma unroll
  for (int mi = 0; mi < 8; mi++)
    #pragma unroll
    for (int nt = 0; nt < 2; nt++)
      #pragma unroll
      for (int c = 0; c < 4; c++) oacc[mi][nt][c] = 0.f;
  float mrow0 = -1e30f, mrow1 = -1e30f, lrow0 = 0.f, lrow1 = 0.f;

  for (int t = 0; t < ntiles; t++) {
    const int k0 = t * 64;
    const int s = t % 3;
    asm volatile("cp.async.wait_group 1;" ::);
    __syncthreads();
    FL_ISSUE(t + 2, (t + 2) % 3);
    if (k0 > qrow_max) continue;

    const unsigned* Ks = St + s * FL_STAGEW;
    const unsigned* Vt = Ks + FL_KWORDS;

    // ---- S = Q K^T (fp16, fp32 accum) ----
    float sacc[8][4];
    #pragma unroll
    for (int nt = 0; nt < 8; nt++)
      #pragma unroll
      for (int c = 0; c < 4; c++) sacc[nt][c] = 0.f;

    #pragma unroll
    for (int ks = 0; ks < 8; ks++) {
      const int wb = 8 * ks + tk;
      const unsigned* qr0 = Qs + (m0 + g) * FL_QPITCH + wb;
      const unsigned* qr1 = Qs + (m0 + 8 + g) * FL_QPITCH + wb;
      const unsigned a0 = qr0[0], a1 = qr1[0], a2 = qr0[4], a3 = qr1[4];
      #pragma unroll
      for (int nt = 0; nt < 8; nt++) {
        const unsigned* kr = Ks + (nt * 8 + g) * FL_QPITCH + wb;
        mma_f16(sacc[nt], a0, a1, a2, a3, kr[0], kr[4]);
      }
    }

    // ---- causal mask (near diagonal only) ----
    if (k0 + 63 > qb + m0) {
      const int r0q = qb + m0 + g, r1q = r0q + 8;
      #pragma unroll
      for (int nt = 0; nt < 8; nt++) {
        const int key0 = k0 + nt * 8 + 2 * tk;
        if (key0     > r0q) sacc[nt][0] = -1e30f;
        if (key0 + 1 > r0q) sacc[nt][1] = -1e30f;
        if (key0     > r1q) sacc[nt][2] = -1e30f;
        if (key0 + 1 > r1q) sacc[nt][3] = -1e30f;
      }
    }

    // ---- online softmax ----
    float mx0 = mrow0, mx1 = mrow1;
    #pragma unroll
    for (int nt = 0; nt < 8; nt++) {
      mx0 = fmaxf(mx0, fmaxf(sacc[nt][0], sacc[nt][1]));
      mx1 = fmaxf(mx1, fmaxf(sacc[nt][2], sacc[nt][3]));
    }
    mx0 = fmaxf(mx0, __shfl_xor_sync(0xffffffffu, mx0, 1));
    mx0 = fmaxf(mx0, __shfl_xor_sync(0xffffffffu, mx0, 2));
    mx1 = fmaxf(mx1, __shfl_xor_sync(0xffffffffu, mx1, 1));
    mx1 = fmaxf(mx1, __shfl_xor_sync(0xffffffffu, mx1, 2));
    const float al0 = __expf(mrow0 - mx0);
    const float al1 = __expf(mrow1 - mx1);
    mrow0 = mx0; mrow1 = mx1;
    lrow0 *= al0; lrow1 *= al1;

    const float af00 = __shfl_sync(0xffffffffu, al0, 8 * tk);
    const float af01 = __shfl_sync(0xffffffffu, al0, 8 * tk + 4);
    const float af10 = __shfl_sync(0xffffffffu, al1, 8 * tk);
    const float af11 = __shfl_sync(0xffffffffu, al1, 8 * tk + 4);
    #pragma unroll
    for (int mi = 0; mi < 8; mi++) {
      oacc[mi][0][0] *= af00; oacc[mi][0][1] *= af01;
      oacc[mi][0][2] *= af00; oacc[mi][0][3] *= af01;
      oacc[mi][1][0] *= af10; oacc[mi][1][1] *= af11;
      oacc[mi][1][2] *= af10; oacc[mi][1][3] *= af11;
    }

    float cb0 = 0.f, cb1 = 0.f;
    #pragma unroll
    for (int nt = 0; nt < 8; nt++) {
      sacc[nt][0] = __expf(sacc[nt][0] - mx0);
      sacc[nt][1] = __expf(sacc[nt][1] - mx0);
      sacc[nt][2] = __expf(sacc[nt][2] - mx1);
      sacc[nt][3] = __expf(sacc[nt][3] - mx1);
      cb0 += sacc[nt][0] + sacc[nt][1];
      cb1 += sacc[nt][2] + sacc[nt][3];
    }
    cb0 += __shfl_xor_sync(0xffffffffu, cb0, 1);
    cb0 += __shfl_xor_sync(0xffffffffu, cb0, 2);
    cb1 += __shfl_xor_sync(0xffffffffu, cb1, 1);
    cb1 += __shfl_xor_sync(0xffffffffu, cb1, 2);
    lrow0 += cb0; lrow1 += cb1;

    // ---- O^T += V^T * P^T (fp16); P^T fragments direct from sacc ----
    #pragma unroll
    for (int ks = 0; ks < 4; ks++) {
      const unsigned bl0 = packh2(sacc[2 * ks][0],     sacc[2 * ks][1]);
      const unsigned bl1 = packh2(sacc[2 * ks + 1][0], sacc[2 * ks + 1][1]);
      const unsigned bh0 = packh2(sacc[2 * ks][2],     sacc[2 * ks][3]);
      const unsigned bh1 = packh2(sacc[2 * ks + 1][2], sacc[2 * ks + 1][3]);
      #pragma unroll
      for (int mi = 0; mi < 8; mi++) {
        const unsigned* vr0 = Vt + (mi * 16 + g) * FL_VPITCH + ks * 8 + tk;
        const unsigned* vr1 = vr0 + 8 * FL_VPITCH;
        const unsigned va0 = vr0[0], va1 = vr1[0], va2 = vr0[4], va3 = vr1[4];
        mma_f16(oacc[mi][0], va0, va1, va2, va3, bl0, bl1);
        mma_f16(oacc[mi][1], va0, va1, va2, va3, bh0, bh1);
      }
    }
  }

  // ---- normalize + store ctx (fp16; O^T layout: m=dh, n=qrow) ----
  const float l00 = __shfl_sync(0xffffffffu, lrow0, 8 * tk);
  const float l01 = __shfl_sync(0xffffffffu, lrow0, 8 * tk + 4);
  const float l10 = __shfl_sync(0xffffffffu, lrow1, 8 * tk);
  const float l11 = __shfl_sync(0xffffffffu, lrow1, 8 * tk + 4);
  const float i00 = 1.f / l00, i01 = 1.f / l01;
  const float i10 = 1.f / l10, i11 = 1.f / l11;

  __half* cp = ctx + ((size_t)(b * NS + qb + m0)) * ND + h * NDH;
  #pragma unroll
  for (int mi = 0; mi < 8; mi++) {
    const int d0 = mi * 16 + g;
    cp[(size_t)(2 * tk) * ND + d0]         = __float2half_rn(oacc[mi][0][0] * i00);
    cp[(size_t)(2 * tk + 1) * ND + d0]     = __float2half_rn(oacc[mi][0][1] * i01);
    cp[(size_t)(2 * tk) * ND + d0 + 8]     = __float2half_rn(oacc[mi][0][2] * i00);
    cp[(size_t)(2 * tk + 1) * ND + d0 + 8] = __float2half_rn(oacc[mi][0][3] * i01);
    cp[(size_t)(8 + 2 * tk) * ND + d0]     = __float2half_rn(oacc[mi][1][0] * i10);
    cp[(size_t)(9 + 2 * tk) * ND + d0]     = __float2half_rn(oacc[mi][1][1] * i11);
    cp[(size_t)(8 + 2 * tk) * ND + d0 + 8] = __float2half_rn(oacc[mi][1][2] * i10);
    cp[(size_t)(9 + 2 * tk) * ND + d0 + 8] = __float2half_rn(oacc[mi][1][3] * i11);
  }
}

extern "C" void kernel_launch(void* const* d_in, const int* in_sizes, int n_in,
                              void* d_out, int out_size) {
  const float* x  = (const float*)d_in[0];
  const float* fc = (const float*)d_in[1];
  const float* fs = (const float*)d_in[2];
  // d_in[3] is the mask; causal handled analytically
  const float* wq = (const float*)d_in[4];
  const float* wk = (const float*)d_in[5];
  const float* wv = (const float*)d_in[6];
  const float* wo = (const float*)d_in[7];

  __half *qh, *kh, *vt, *ctx, *xh, *wqh, *wkh, *wvh, *woh;
  cudaGetSymbolAddress((void**)&qh,  g_qh);
  cudaGetSymbolAddress((void**)&kh,  g_kh);
  cudaGetSymbolAddress((void**)&vt,  g_vt);
  cudaGetSymbolAddress((void**)&ctx, g_ctx);
  cudaGetSymbolAddress((void**)&xh,  g_xh);
  cudaGetSymbolAddress((void**)&wqh, g_wqh);
  cudaGetSymbolAddress((void**)&wkh, g_wkh);
  cudaGetSymbolAddress((void**)&wvh, g_wvh);
  cudaGetSymbolAddress((void**)&woh, g_woh);

  cudaFuncSetAttribute(flash_tc, cudaFuncAttributeMaxDynamicSharedMemorySize, FL_SMEM);
  cudaFuncSetAttribute(gemm_h<0>, cudaFuncAttributeMaxDynamicSharedMemorySize, GH_SMEM);
  cudaFuncSetAttribute(gemm_h<2>, cudaFuncAttributeMaxDynamicSharedMemorySize, GH_SMEM);
  cudaFuncSetAttribute(gemm_h<3>, cudaFuncAttributeMaxDynamicSharedMemorySize, GH_SMEM);

  // Prep: convert x + all 4 weights to fp16 (2 launches).
  const int nx4 = NM * ND / 4;
  tohalf_k<<<nx4 / 256, 256>>>(x, xh, nx4);
  tohalf4_k<<<4 * (ND * ND / 4) / 256, 256>>>(wq, wk, wv, wo, wqh, wkh, wvh, woh);

  const float scale = 0.08838834764831845f;  // 1/sqrt(128)
  dim3 gg(ND / 128, NM / 128);
  gemm_h<2><<<gg, 256, GH_SMEM>>>(xh, wqh, nullptr, qh, fc, fs, scale);
  gemm_h<2><<<gg, 256, GH_SMEM>>>(xh, wkh, nullptr, kh, fc, fs, 1.0f);
  gemm_h<3><<<gg, 256, GH_SMEM>>>(xh, wvh, nullptr, vt, nullptr, nullptr, 1.0f);

  dim3 fg(NS / 128, NB * NH);
  flash_tc<<<fg, 256, FL_SMEM>>>(qh, kh, vt, ctx);

  gemm_h<0><<<gg, 256, GH_SMEM>>>(ctx, woh, (float*)d_out, nullptr, nullptr, nullptr, 1.0f);
}

// round 10
// speedup vs baseline: 11.8404x; 1.0515x over previous
#include <cuda_runtime.h>
#include <cuda_fp16.h>
#include <stdint.h>
#include <math.h>

#define NB 2
#define NS 2048
#define ND 2048
#define NH 16
#define NDH 128
#define NM (NB*NS)

// Scratch (device globals; no allocation allowed)
__device__ __half g_qh[(size_t)NB*NH*NS*NDH];
__device__ __half g_kh[(size_t)NB*NH*NS*NDH];
__device__ __half g_vt[(size_t)NB*NH*NDH*NS];   // V transposed: [b,h,dh,s] fp16
__device__ __half g_ctx[(size_t)NB*NS*ND];      // attention output, fp16
__device__ __half g_xh[(size_t)NM*ND];          // x in fp16
__device__ __half g_wqh[(size_t)ND*ND];
__device__ __half g_wkh[(size_t)ND*ND];
__device__ __half g_wvh[(size_t)ND*ND];
__device__ __half g_woh[(size_t)ND*ND];

__device__ __forceinline__ unsigned packh2(float lo, float hi) {
  __half2 h = __floats2half2_rn(lo, hi);
  return *(unsigned*)&h;
}
__device__ __forceinline__ void mma_f16(float* c, unsigned a0, unsigned a1,
                                        unsigned a2, unsigned a3,
                                        unsigned b0, unsigned b1) {
  asm volatile(
    "mma.sync.aligned.m16n8k16.row.col.f32.f16.f16.f32 "
    "{%0,%1,%2,%3},{%4,%5,%6,%7},{%8,%9},{%0,%1,%2,%3};\n"
    : "+f"(c[0]), "+f"(c[1]), "+f"(c[2]), "+f"(c[3])
    : "r"(a0), "r"(a1), "r"(a2), "r"(a3), "r"(b0), "r"(b1));
}
__device__ __forceinline__ void ldsm4(unsigned& r0, unsigned& r1,
                                      unsigned& r2, unsigned& r3,
                                      uint32_t addr) {
  asm volatile(
    "ldmatrix.sync.aligned.m8n8.x4.shared.b16 {%0,%1,%2,%3}, [%4];"
    : "=r"(r0), "=r"(r1), "=r"(r2), "=r"(r3) : "r"(addr));
}
__device__ __forceinline__ void cpasync16(uint32_t dst, const void* src) {
  asm volatile("cp.async.cg.shared.global [%0], [%1], 16;" :: "r"(dst),
               "l"(src));
}

// fp32 -> fp16 conversion, vectorized.
__global__ void tohalf_k(const float* __restrict__ src,
                         __half* __restrict__ dst, int n4) {
  int i = blockIdx.x * 256 + threadIdx.x;
  if (i < n4) {
    float4 v = ((const float4*)src)[i];
    __half2 h0 = __floats2half2_rn(v.x, v.y);
    __half2 h1 = __floats2half2_rn(v.z, v.w);
    uint2 u = {*(unsigned*)&h0, *(unsigned*)&h1};
    ((uint2*)dst)[i] = u;
  }
}

// 4 weight matrices (ND*ND each) in one launch.
__global__ void tohalf4_k(const float* __restrict__ s0, const float* __restrict__ s1,
                          const float* __restrict__ s2, const float* __restrict__ s3,
                          __half* __restrict__ d0, __half* __restrict__ d1,
                          __half* __restrict__ d2, __half* __restrict__ d3) {
  const int per = (ND * ND / 4) / 256;       // blocks per tensor
  const int which = blockIdx.x / per;
  const int i = (blockIdx.x % per) * 256 + threadIdx.x;
  const float* src = (which == 0) ? s0 : (which == 1) ? s1 : (which == 2) ? s2 : s3;
  __half* dst = (which == 0) ? d0 : (which == 1) ? d1 : (which == 2) ? d2 : d3;
  float4 v = ((const float4*)src)[i];
  __half2 h0 = __floats2half2_rn(v.x, v.y);
  __half2 h1 = __floats2half2_rn(v.z, v.w);
  uint2 u = {*(unsigned*)&h0, *(unsigned*)&h1};
  ((uint2*)dst)[i] = u;
}

// ============================================================================
// GEMM: fp16 mma.sync + ldmatrix fragment loads, cp.async 3-stage, 128x128.
// ============================================================================
#define GH_STAGEW 2560                 // 128 rows * 20 words
#define GH_SMEM (3 * 2 * GH_STAGEW * 4)

template<int MODE>
__global__ void __launch_bounds__(256, 2) gemm_h(
    const __half* __restrict__ A, const __half* __restrict__ W,
    float* __restrict__ C, __half* __restrict__ Ch,
    const float* __restrict__ fcos, const float* __restrict__ fsin,
    float outscale)
{
  extern __shared__ unsigned smh[];
  unsigned* As = smh;                    // [3][128][20]
  unsigned* Bs = smh + 3 * GH_STAGEW;
  const int K = ND;
  const int bm = blockIdx.y * 128;
  const int bn = blockIdx.x * 128;
  const int tid = threadIdx.x;
  const int warp = tid >> 5, lane = tid & 31;
  const int wm0 = (warp >> 2) * 64;
  const int wn0 = (warp & 3) * 32;
  const int g = lane >> 2, tk = lane & 3;
  const int l8 = lane & 7, lm = lane >> 3;   // ldmatrix: row-in-8x8, matrix id

  const uint32_t sa = (uint32_t)__cvta_generic_to_shared(As);
  const uint32_t sbm = (uint32_t)__cvta_generic_to_shared(Bs);

  // Per-thread ldmatrix byte offsets within a stage (add ks*32 for k-halves).
  // A (a0..a3 = [m0-7,k0-7],[m8-15,k0-7],[m0-7,k8-15],[m8-15,k8-15]):
  uint32_t aoff[4];
  #pragma unroll
  for (int mi = 0; mi < 4; mi++)
    aoff[mi] = (uint32_t)(((wm0 + mi * 16 + l8 + (lm & 1) * 8) * 20
                           + (lm >> 1) * 4) * 4);
  // B (mat0..3 = [n0-7,k0-7],[n0-7,k8-15],[n8-15,k0-7],[n8-15,k8-15]):
  uint32_t boff[2];
  #pragma unroll
  for (int n2 = 0; n2 < 2; n2++)
    boff[n2] = (uint32_t)(((wn0 + n2 * 16 + l8 + (lm >> 1) * 8) * 20
                           + (lm & 1) * 4) * 4);

  float acc[4][4][4];
  #pragma unroll
  for (int mi = 0; mi < 4; mi++)
    #pragma unroll
    for (int ni = 0; ni < 4; ni++)
      #pragma unroll
      for (int cc = 0; cc < 4; cc++) acc[mi][ni][cc] = 0.f;

  #define GH_ISSUE(kt, st) do { \
    _Pragma("unroll") \
    for (int i = 0; i < 2; i++) { \
      const int id = tid + 256 * i; \
      const int r = id >> 2, c = id & 3; \
      const uint32_t wo = (uint32_t)((st) * GH_STAGEW + r * 20 + c * 4) * 4; \
      cpasync16(sa + wo, A + (size_t)(bm + r) * K + (kt) * 32 + c * 8); \
      cpasync16(sbm + wo, W + (size_t)(bn + r) * K + (kt) * 32 + c * 8); \
    } \
    asm volatile("cp.async.commit_group;" ::); \
  } while (0)

  GH_ISSUE(0, 0);
  GH_ISSUE(1, 1);

  const int niter = K / 32;   // 64
  int st_c = 0, st_p = 2;
  for (int kt = 0; kt < niter; kt++) {
    asm volatile("cp.async.wait_group 1;" ::);
    __syncthreads();
    if (kt + 2 < niter) GH_ISSUE(kt + 2, st_p);
    else asm volatile("cp.async.commit_group;" ::);

    const uint32_t ab = sa + (uint32_t)st_c * GH_STAGEW * 4;
    const uint32_t bb = sbm + (uint32_t)st_c * GH_STAGEW * 4;
    #pragma unroll
    for (int ks = 0; ks < 2; ks++) {
      unsigned afr[4][4], bfr[4][2];
      #pragma unroll
      for (int mi = 0; mi < 4; mi++)
        ldsm4(afr[mi][0], afr[mi][1], afr[mi][2], afr[mi][3],
              ab + aoff[mi] + ks * 32);
      #pragma unroll
      for (int n2 = 0; n2 < 2; n2++)
        ldsm4(bfr[2 * n2][0], bfr[2 * n2][1], bfr[2 * n2 + 1][0],
              bfr[2 * n2 + 1][1], bb + boff[n2] + ks * 32);
      #pragma unroll
      for (int mi = 0; mi < 4; mi++)
        #pragma unroll
        for (int ni = 0; ni < 4; ni++)
          mma_f16(acc[mi][ni], afr[mi][0], afr[mi][1], afr[mi][2], afr[mi][3],
                  bfr[ni][0], bfr[ni][1]);
    }
    st_c = (st_c == 2) ? 0 : st_c + 1;
    st_p = (st_p == 2) ? 0 : st_p + 1;
    __syncthreads();
  }

  #pragma unroll
  for (int mi = 0; mi < 4; mi++) {
    #pragma unroll
    for (int half = 0; half < 2; half++) {
      const int m = bm + wm0 + mi * 16 + g + half * 8;
      const int b = m / NS, s = m % NS;
      #pragma unroll
      for (int ni = 0; ni < 4; ni++) {
        float v0 = acc[mi][ni][half * 2 + 0];
        float v1 = acc[mi][ni][half * 2 + 1];
        const int n = bn + wn0 + ni * 8 + tk * 2;
        if (MODE == 0) {
          float2 vv = {v0, v1};
          *(float2*)&C[(size_t)m * ND + n] = vv;
        } else if (MODE == 3) {
          const int h = n / NDH, d = n % NDH;
          __half* dst = Ch + (((size_t)(b * NH + h)) * NDH + d) * NS + s;
          dst[0]  = __float2half_rn(v0);
          dst[NS] = __float2half_rn(v1);
        } else {  // MODE 2
          const int h = n / NDH, d = n % NDH;
          __half* dst = Ch + (((size_t)(b * NH + h)) * NS + s) * NDH;
          const int pi = d >> 1;
          const float cc = fcos[s * (NDH / 2) + pi];
          const float sn = fsin[s * (NDH / 2) + pi];
          v0 *= outscale; v1 *= outscale;
          __half2 vv = __floats2half2_rn(v0 * cc - v1 * sn, v0 * sn + v1 * cc);
          *(__half2*)&dst[d] = vv;
        }
      }
    }
  }
}

// ============================================================================
// Flash attention (causal), fp16 mma + ldmatrix, cp.async 3-stage K/V ring.
// Br=128 (8 warps x 16 rows), Bc=64.
// ============================================================================
#define FL_QPITCH 68
#define FL_VPITCH 36
#define FL_KWORDS (64 * FL_QPITCH)                 // 4352
#define FL_VWORDS (128 * FL_VPITCH)                // 4608
#define FL_STAGEW (FL_KWORDS + FL_VWORDS)          // 8960
#define FL_SMEM ((128 * FL_QPITCH + 3 * FL_STAGEW) * 4)

__global__ void __launch_bounds__(256) flash_tc(
    const __half* __restrict__ gq, const __half* __restrict__ gk,
    const __half* __restrict__ gvt, __half* __restrict__ ctx)
{
  extern __shared__ unsigned smf[];
  unsigned* Qs = smf;
  unsigned* St = smf + 128 * FL_QPITCH;   // 3 stages

  const int bh = blockIdx.y;
  const int b = bh >> 4, h = bh & 15;
  const int qb = blockIdx.x * 128;
  const int tid = threadIdx.x;
  const int warp = tid >> 5, lane = tid & 31;
  const int g = lane >> 2, tk = lane & 3;
  const int l8 = lane & 7, lm = lane >> 3;
  const int m0 = warp * 16;
  const int qrow_max = qb + m0 + 15;

  const __half* kbase = gk + (size_t)bh * NS * NDH;
  const __half* vtb = gvt + (size_t)bh * NDH * NS;
  const int ntiles = qb / 64 + 2;
  const uint32_t sQs = (uint32_t)__cvta_generic_to_shared(Qs);
  const uint32_t sSt = (uint32_t)__cvta_generic_to_shared(St);

  // ldmatrix byte offsets:
  // Q (A-frag, rows m0..m0+15): + ks*32
  const uint32_t qoff = sQs +
    (uint32_t)(((m0 + l8 + (lm & 1) * 8) * FL_QPITCH + (lm >> 1) * 4) * 4);
  // K (B-frag, covers n = 16*n2 .. +15): stage-relative, + ks*32
  uint32_t koff[4];
  #pragma unroll
  for (int n2 = 0; n2 < 4; n2++)
    koff[n2] = (uint32_t)(((n2 * 16 + l8 + (lm >> 1) * 8) * FL_QPITCH
                           + (lm & 1) * 4) * 4);
  // V (A-frag, rows mi*16..+15): stage-relative (+ FL_KWORDS), + ks*32
  uint32_t voff[8];
  #pragma unroll
  for (int mi = 0; mi < 8; mi++)
    voff[mi] = (uint32_t)((FL_KWORDS + (mi * 16 + l8 + (lm & 1) * 8) * FL_VPITCH
                           + (lm >> 1) * 4) * 4);

  // cp.async issue of K/V tile t into stage s (empty-commit past the end)
  #define FL_ISSUE(t, s) do { \
    if ((t) < ntiles) { \
      const int k0i = (t) * 64; \
      const uint32_t kd = sSt + (uint32_t)(s) * FL_STAGEW * 4; \
      const uint32_t vd = kd + FL_KWORDS * 4; \
      _Pragma("unroll") \
      for (int i = 0; i < 4; i++) { \
        const int id = tid + 256 * i; \
        const int kr = id >> 4, kc = id & 15; \
        cpasync16(kd + (uint32_t)(kr * FL_QPITCH + kc * 4) * 4, \
                  kbase + (size_t)(k0i + kr) * NDH + kc * 8); \
        const int vr = id >> 3, vc = id & 7; \
        cpasync16(vd + (uint32_t)(vr * FL_VPITCH + vc * 4) * 4, \
                  vtb + (size_t)vr * NS + k0i + vc * 8); \
      } \
    } \
    asm volatile("cp.async.commit_group;" ::); \
  } while (0)

  FL_ISSUE(0, 0);
  FL_ISSUE(1, 1);

  // Load Q tile (scale already folded in by the Q-GEMM)
  const __half* qbase = gq + ((size_t)bh * NS + qb) * NDH;
  #pragma unroll
  for (int i = 0; i < 8; i++) {
    int idx = i * 256 + tid;
    int row = idx >> 4, c = idx & 15;
    uint4 v = *(const uint4*)(qbase + (size_t)row * NDH + c * 8);
    *(uint4*)(Qs + row * FL_QPITCH + c * 4) = v;
  }

  float oacc[8][2][4];
  #pragma unroll
  for (int mi = 0; mi < 8; mi++)
    #pragma unroll
    for (int nt = 0; nt < 2; nt++)
      #pragma unroll
      for (int c = 0; c < 4; c++) oacc[mi][nt][c] = 0.f;
  float mrow0 = -1e30f, mrow1 = -1e30f, lrow0 = 0.f, lrow1 = 0.f;

  for (int t = 0; t < ntiles; t++) {
    const int k0 = t * 64;
    const int s = t % 3;
    asm volatile("cp.async.wait_group 1;" ::);
    __syncthreads();
    FL_ISSUE(t + 2, (t + 2) % 3);
    if (k0 > qrow_max) continue;

    const uint32_t stb = sSt + (uint32_t)s * FL_STAGEW * 4;

    // ---- S = Q K^T (fp16, fp32 accum) ----
    float sacc[8][4];
    #pragma unroll
    for (int nt = 0; nt < 8; nt++)
      #pragma unroll
      for (int c = 0; c < 4; c++) sacc[nt][c] = 0.f;

    #pragma unroll
    for (int ks = 0; ks < 8; ks++) {
      unsigned a0, a1, a2, a3;
      ldsm4(a0, a1, a2, a3, qoff + ks * 32);
      unsigned kf[8][2];
      #pragma unroll
      for (int n2 = 0; n2 < 4; n2++)
        ldsm4(kf[2 * n2][0], kf[2 * n2][1], kf[2 * n2 + 1][0],
              kf[2 * n2 + 1][1], stb + koff[n2] + ks * 32);
      #pragma unroll
      for (int nt = 0; nt < 8; nt++)
        mma_f16(sacc[nt], a0, a1, a2, a3, kf[nt][0], kf[nt][1]);
    }

    // ---- causal mask (near diagonal only) ----
    if (k0 + 63 > qb + m0) {
      const int r0q = qb + m0 + g, r1q = r0q + 8;
      #pragma unroll
      for (int nt = 0; nt < 8; nt++) {
        const int key0 = k0 + nt * 8 + 2 * tk;
        if (key0     > r0q) sacc[nt][0] = -1e30f;
        if (key0 + 1 > r0q) sacc[nt][1] = -1e30f;
        if (key0     > r1q) sacc[nt][2] = -1e30f;
        if (key0 + 1 > r1q) sacc[nt][3] = -1e30f;
      }
    }

    // ---- online softmax ----
    float mx0 = mrow0, mx1 = mrow1;
    #pragma unroll
    for (int nt = 0; nt < 8; nt++) {
      mx0 = fmaxf(mx0, fmaxf(sacc[nt][0], sacc[nt][1]));
      mx1 = fmaxf(mx1, fmaxf(sacc[nt][2], sacc[nt][3]));
    }
    mx0 = fmaxf(mx0, __shfl_xor_sync(0xffffffffu, mx0, 1));
    mx0 = fmaxf(mx0, __shfl_xor_sync(0xffffffffu, mx0, 2));
    mx1 = fmaxf(mx1, __shfl_xor_sync(0xffffffffu, mx1, 1));
    mx1 = fmaxf(mx1, __shfl_xor_sync(0xffffffffu, mx1, 2));
    const float al0 = __expf(mrow0 - mx0);
    const float al1 = __expf(mrow1 - mx1);
    mrow0 = mx0; mrow1 = mx1;
    lrow0 *= al0; lrow1 *= al1;

    const float af00 = __shfl_sync(0xffffffffu, al0, 8 * tk);
    const float af01 = __shfl_sync(0xffffffffu, al0, 8 * tk + 4);
    const float af10 = __shfl_sync(0xffffffffu, al1, 8 * tk);
    const float af11 = __shfl_sync(0xffffffffu, al1, 8 * tk + 4);
    #pragma unroll
    for (int mi = 0; mi < 8; mi++) {
      oacc[mi][0][0] *= af00; oacc[mi][0][1] *= af01;
      oacc[mi][0][2] *= af00; oacc[mi][0][3] *= af01;
      oacc[mi][1][0] *= af10; oacc[mi][1][1] *= af11;
      oacc[mi][1][2] *= af10; oacc[mi][1][3] *= af11;
    }

    float cb0 = 0.f, cb1 = 0.f;
    #pragma unroll
    for (int nt = 0; nt < 8; nt++) {
      sacc[nt][0] = __expf(sacc[nt][0] - mx0);
      sacc[nt][1] = __expf(sacc[nt][1] - mx0);
      sacc[nt][2] = __expf(sacc[nt][2] - mx1);
      sacc[nt][3] = __expf(sacc[nt][3] - mx1);
      cb0 += sacc[nt][0] + sacc[nt][1];
      cb1 += sacc[nt][2] + sacc[nt][3];
    }
    cb0 += __shfl_xor_sync(0xffffffffu, cb0, 1);
    cb0 += __shfl_xor_sync(0xffffffffu, cb0, 2);
    cb1 += __shfl_xor_sync(0xffffffffu, cb1, 1);
    cb1 += __shfl_xor_sync(0xffffffffu, cb1, 2);
    lrow0 += cb0; lrow1 += cb1;

    // ---- O^T += V^T * P^T (fp16); P^T fragments direct from sacc ----
    #pragma unroll
    for (int ks = 0; ks < 4; ks++) {
      const unsigned bl0 = packh2(sacc[2 * ks][0],     sacc[2 * ks][1]);
      const unsigned bl1 = packh2(sacc[2 * ks + 1][0], sacc[2 * ks + 1][1]);
      const unsigned bh0 = packh2(sacc[2 * ks][2],     sacc[2 * ks][3]);
      const unsigned bh1 = packh2(sacc[2 * ks + 1][2], sacc[2 * ks + 1][3]);
      #pragma unroll
      for (int mi = 0; mi < 8; mi++) {
        unsigned va0, va1, va2, va3;
        ldsm4(va0, va1, va2, va3, stb + voff[mi] + ks * 32);
        mma_f16(oacc[mi][0], va0, va1, va2, va3, bl0, bl1);
        mma_f16(oacc[mi][1], va0, va1, va2, va3, bh0, bh1);
      }
    }
  }

  // ---- normalize + store ctx (fp16; O^T layout: m=dh, n=qrow) ----
  const float l00 = __shfl_sync(0xffffffffu, lrow0, 8 * tk);
  const float l01 = __shfl_sync(0xffffffffu, lrow0, 8 * tk + 4);
  const float l10 = __shfl_sync(0xffffffffu, lrow1, 8 * tk);
  const float l11 = __shfl_sync(0xffffffffu, lrow1, 8 * tk + 4);
  const float i00 = 1.f / l00, i01 = 1.f / l01;
  const float i10 = 1.f / l10, i11 = 1.f / l11;

  __half* cp = ctx + ((size_t)(b * NS + qb + m0)) * ND + h * NDH;
  #pragma unroll
  for (int mi = 0; mi < 8; mi++) {
    const int d0 = mi * 16 + g;
    cp[(size_t)(2 * tk) * ND + d0]         = __float2half_rn(oacc[mi][0][0] * i00);
    cp[(size_t)(2 * tk + 1) * ND + d0]     = __float2half_rn(oacc[mi][0][1] * i01);
    cp[(size_t)(2 * tk) * ND + d0 + 8]     = __float2half_rn(oacc[mi][0][2] * i00);
    cp[(size_t)(2 * tk + 1) * ND + d0 + 8] = __float2half_rn(oacc[mi][0][3] * i01);
    cp[(size_t)(8 + 2 * tk) * ND + d0]     = __float2half_rn(oacc[mi][1][0] * i10);
    cp[(size_t)(9 + 2 * tk) * ND + d0]     = __float2half_rn(oacc[mi][1][1] * i11);
    cp[(size_t)(8 + 2 * tk) * ND + d0 + 8] = __float2half_rn(oacc[mi][1][2] * i10);
    cp[(size_t)(9 + 2 * tk) * ND + d0 + 8] = __float2half_rn(oacc[mi][1][3] * i11);
  }
}

extern "C" void kernel_launch(void* const* d_in, const int* in_sizes, int n_in,
                              void* d_out, int out_size) {
  const float* x  = (const float*)d_in[0];
  const float* fc = (const float*)d_in[1];
  const float* fs = (const float*)d_in[2];
  // d_in[3] is the mask; causal handled analytically
  const float* wq = (const float*)d_in[4];
  const float* wk = (const float*)d_in[5];
  const float* wv = (const float*)d_in[6];
  const float* wo = (const float*)d_in[7];

  __half *qh, *kh, *vt, *ctx, *xh, *wqh, *wkh, *wvh, *woh;
  cudaGetSymbolAddress((void**)&qh,  g_qh);
  cudaGetSymbolAddress((void**)&kh,  g_kh);
  cudaGetSymbolAddress((void**)&vt,  g_vt);
  cudaGetSymbolAddress((void**)&ctx, g_ctx);
  cudaGetSymbolAddress((void**)&xh,  g_xh);
  cudaGetSymbolAddress((void**)&wqh, g_wqh);
  cudaGetSymbolAddress((void**)&wkh, g_wkh);
  cudaGetSymbolAddress((void**)&wvh, g_wvh);
  cudaGetSymbolAddress((void**)&woh, g_woh);

  cudaFuncSetAttribute(flash_tc, cudaFuncAttributeMaxDynamicSharedMemorySize, FL_SMEM);
  cudaFuncSetAttribute(gemm_h<0>, cudaFuncAttributeMaxDynamicSharedMemorySize, GH_SMEM);
  cudaFuncSetAttribute(gemm_h<2>, cudaFuncAttributeMaxDynamicSharedMemorySize, GH_SMEM);
  cudaFuncSetAttribute(gemm_h<3>, cudaFuncAttributeMaxDynamicSharedMemorySize, GH_SMEM);

  // Prep: convert x + all 4 weights to fp16 (2 launches).
  const int nx4 = NM * ND / 4;
  tohalf_k<<<nx4 / 256, 256>>>(x, xh, nx4);
  tohalf4_k<<<4 * (ND * ND / 4) / 256, 256>>>(wq, wk, wv, wo, wqh, wkh, wvh, woh);

  const float scale = 0.08838834764831845f;  // 1/sqrt(128)
  dim3 gg(ND / 128, NM / 128);
  gemm_h<2><<<gg, 256, GH_SMEM>>>(xh, wqh, nullptr, qh, fc, fs, scale);
  gemm_h<2><<<gg, 256, GH_SMEM>>>(xh, wkh, nullptr, kh, fc, fs, 1.0f);
  gemm_h<3><<<gg, 256, GH_SMEM>>>(xh, wvh, nullptr, vt, nullptr, nullptr, 1.0f);

  dim3 fg(NS / 128, NB * NH);
  flash_tc<<<fg, 256, FL_SMEM>>>(qh, kh, vt, ctx);

  gemm_h<0><<<gg, 256, GH_SMEM>>>(ctx, woh, (float*)d_out, nullptr, nullptr, nullptr, 1.0f);
}